// round 11
// baseline (speedup 1.0000x reference)
#include <cuda_runtime.h>
#include <cuda_bf16.h>
#include <stdint.h>

#define NWIN   512
#define T_     64
#define C_     512
#define NH_    8
#define D_     64
#define MROWS  32768        // NWIN * T_
#define N_QKV  1536
#define SCALE_ 0.125f

// ---------------- scratch ----------------
__device__ __nv_bfloat16 g_xw [MROWS * C_];      // gathered+rolled x, bf16
__device__ __nv_bfloat16 g_qkv[MROWS * N_QKV];   // Q|K|V concat
__device__ __nv_bfloat16 g_o  [MROWS * C_];      // attention out
__device__ __nv_bfloat16 g_wT [N_QKV * C_];      // [out col][k]
__device__ __nv_bfloat16 g_woT[C_ * C_];         // [out c][k=hd]

// ---------------- asm helpers ----------------
__device__ __forceinline__ void mma16816(float* c, uint32_t a0, uint32_t a1, uint32_t a2, uint32_t a3,
                                         uint32_t b0, uint32_t b1) {
    asm volatile(
        "mma.sync.aligned.m16n8k16.row.col.f32.bf16.bf16.f32 "
        "{%0,%1,%2,%3}, {%4,%5,%6,%7}, {%8,%9}, {%0,%1,%2,%3};"
        : "+f"(c[0]), "+f"(c[1]), "+f"(c[2]), "+f"(c[3])
        : "r"(a0), "r"(a1), "r"(a2), "r"(a3), "r"(b0), "r"(b1));
}
__device__ __forceinline__ void ldsm4(uint32_t* r, uint32_t addr) {
    asm volatile("ldmatrix.sync.aligned.m8n8.x4.shared.b16 {%0,%1,%2,%3}, [%4];"
                 : "=r"(r[0]), "=r"(r[1]), "=r"(r[2]), "=r"(r[3]) : "r"(addr));
}
__device__ __forceinline__ void ldsm4t(uint32_t* r, uint32_t addr) {
    asm volatile("ldmatrix.sync.aligned.m8n8.x4.trans.shared.b16 {%0,%1,%2,%3}, [%4];"
                 : "=r"(r[0]), "=r"(r[1]), "=r"(r[2]), "=r"(r[3]) : "r"(addr));
}
__device__ __forceinline__ void cp16(uint32_t smem_dst, const void* gmem_src) {
    asm volatile("cp.async.cg.shared.global [%0], [%1], 16;" :: "r"(smem_dst), "l"(gmem_src));
}
__device__ __forceinline__ void cp_commit() { asm volatile("cp.async.commit_group;"); }
template<int N> __device__ __forceinline__ void cp_wait() { asm volatile("cp.async.wait_group %0;" :: "n"(N)); }
__device__ __forceinline__ uint32_t smem_u32(const void* p) {
    return (uint32_t)__cvta_generic_to_shared(p);
}
__device__ __forceinline__ uint32_t pack_bf16(float a, float b) {
    __nv_bfloat162 t = __floats2bfloat162_rn(a, b);
    return *reinterpret_cast<uint32_t*>(&t);
}

// XOR-swizzled address of 16B chunk c (0..3) of logical 64B row `row`
// within a stage. Conflict-free for ldsm.x4 reads and cp.async stores.
__device__ __forceinline__ uint32_t sw_addr(int row, int c) {
    return (uint32_t)(((row >> 1) << 7) + (((((row & 1) << 2) | c) ^ ((row >> 1) & 7)) << 4));
}

// ---------------- K0: fused weight-convert + input-gather ----------------
__global__ __launch_bounds__(256) void prep_kernel(const float* __restrict__ x,
                                                   const float* __restrict__ wq,
                                                   const float* __restrict__ wk,
                                                   const float* __restrict__ wv,
                                                   const float* __restrict__ wo) {
    if (blockIdx.x < 1024) {
        int idx = blockIdx.x * 256 + threadIdx.x;     // 0..262143
        int r = idx >> 9;
        int j = idx & 511;
        g_wT[j * C_ + r]          = __float2bfloat16(wq[idx]);
        g_wT[(512 + j) * C_ + r]  = __float2bfloat16(wk[idx]);
        g_wT[(1024 + j) * C_ + r] = __float2bfloat16(wv[idx]);
        g_woT[j * C_ + r]         = __float2bfloat16(wo[idx]);
    } else {
        int idx = (blockIdx.x - 1024) * 256 + threadIdx.x;  // 0..4194303
        int row = idx >> 7;
        int ch  = idx & 127;
        int win = row >> 6, t = row & 63;
        int b = win >> 6, wh = (win >> 3) & 7, ww = win & 7;
        int i = t >> 3, j = t & 7;
        int r  = (wh * 8 + i + 4) & 63;
        int cc = (ww * 8 + j + 4) & 63;
        float4 f = *reinterpret_cast<const float4*>(x + (((b * 64 + r) * 64 + cc) << 9) + ch * 4);
        uint2 o;
        o.x = pack_bf16(f.x, f.y);
        o.y = pack_bf16(f.z, f.w);
        *reinterpret_cast<uint2*>(g_xw + row * C_ + ch * 4) = o;
    }
}

// ---------------- GEMM config: BM=128, BN=256, BK=32, S=5, 512 threads ----------------
// 16 warps 4x4 -> warp tile 32x64, acc 64 regs. Swizzled stage: 384 rows x 64B = 24KB.
#define BK_         32
#define STAGE_BYTES 24576
#define S_          5
#define SMEM_DYN    (S_ * STAGE_BYTES)      // 122880 B
#define NCHUNK_     (C_ / BK_)              // 16

// load one BK=32 chunk of A[128xBK] + B[256xBK] into stage `st` (swizzled).
// 1536 cp16 total (3 per thread of 512). logical row: 0..127 A, 128..383 B.
__device__ __forceinline__ void load_chunk(uint32_t dsm, int st,
                                           const __nv_bfloat16* Ag,
                                           const __nv_bfloat16* Bg,
                                           int ko, int tid) {
    const uint32_t base = dsm + st * STAGE_BYTES;
    #pragma unroll
    for (int i = 0; i < 3; i++) {
        int idx = tid + i * 512;          // 0..1535
        int row = idx >> 2, c = idx & 3;
        const __nv_bfloat16* src = (row < 128)
            ? (Ag + (size_t)row * C_ + ko + c * 8)
            : (Bg + (size_t)(row - 128) * C_ + ko + c * 8);
        cp16(base + sw_addr(row, c), src);
    }
}

// mainloop: 16 chunks, 5-stage pipeline, wait<3>, one barrier per chunk.
// acc[2][8][4] per thread (warp tile 32x64, warps 4x4)
__device__ __forceinline__ void gemm_mainloop(uint32_t dsm,
                                              const __nv_bfloat16* Ag,
                                              const __nv_bfloat16* Bg,
                                              float acc[2][8][4]) {
    const int tid = threadIdx.x, lane = tid & 31, warp = tid >> 5;
    const int wm = warp >> 2, wn = warp & 3;     // 4 x 4

    // per-lane swizzled fragment offsets (within stage); +1024B per 16 rows.
    const int r_a = wm * 32 + (lane & 15);
    const int c_a = lane >> 4;                         // 0..1
    const uint32_t aOff0 = sw_addr(r_a, c_a);
    const uint32_t aOff1 = sw_addr(r_a, c_a + 2);
    const int r_b = 128 + wn * 64 + ((lane >> 4) & 1) * 8 + (lane & 7);
    const int c_b = (lane >> 3) & 1;
    const uint32_t bOff0 = sw_addr(r_b, c_b);
    const uint32_t bOff1 = sw_addr(r_b, c_b + 2);

    // prologue: chunks 0..3 -> stages 0..3
    load_chunk(dsm, 0, Ag, Bg, 0, tid);
    cp_commit();
    load_chunk(dsm, 1, Ag, Bg, BK_, tid);
    cp_commit();
    load_chunk(dsm, 2, Ag, Bg, 2 * BK_, tid);
    cp_commit();
    load_chunk(dsm, 3, Ag, Bg, 3 * BK_, tid);
    cp_commit();

    int s = 0;                 // stage of chunk kc
    int sl = 4;                // stage for chunk kc+4
    for (int kc = 0; kc < NCHUNK_; kc++) {
        cp_wait<3>();
        __syncthreads();
        if (kc < NCHUNK_ - 4) load_chunk(dsm, sl, Ag, Bg, (kc + 4) * BK_, tid);
        cp_commit();

        const uint32_t stbase = dsm + s * STAGE_BYTES;
        #pragma unroll
        for (int ks = 0; ks < 2; ks++) {
            const uint32_t aOff = stbase + (ks ? aOff1 : aOff0);
            const uint32_t bOff = stbase + (ks ? bOff1 : bOff0);
            uint32_t a[2][4], bb[4][4];
            #pragma unroll
            for (int mi = 0; mi < 2; mi++)
                ldsm4(a[mi], aOff + mi * 1024);
            #pragma unroll
            for (int p = 0; p < 4; p++)
                ldsm4(bb[p], bOff + p * 1024);
            #pragma unroll
            for (int mi = 0; mi < 2; mi++)
                #pragma unroll
                for (int nt = 0; nt < 8; nt++)
                    mma16816(acc[mi][nt], a[mi][0], a[mi][1], a[mi][2], a[mi][3],
                             bb[nt >> 1][(nt & 1) * 2], bb[nt >> 1][(nt & 1) * 2 + 1]);
        }
        s = (s == S_ - 1) ? 0 : s + 1;
        sl = (sl == S_ - 1) ? 0 : sl + 1;
    }
}

// ---------------- K1: QKV GEMM  [32768,512] x [512,1536] ----------------
__global__ __launch_bounds__(512, 1) void qkv_kernel(const float* __restrict__ bq,
                                                     const float* __restrict__ bk,
                                                     const float* __restrict__ bv) {
    extern __shared__ char dyn[];
    const int tid = threadIdx.x, lane = tid & 31, warp = tid >> 5;
    const int g = lane >> 2, tg = lane & 3;
    const int wm = warp >> 2, wn = warp & 3;
    const int mbase = blockIdx.y * 128, nbase = blockIdx.x * 256;

    const __nv_bfloat16* Ag = g_xw + (size_t)mbase * C_;
    const __nv_bfloat16* Bg = g_wT + (size_t)nbase * C_;

    float acc[2][8][4];
    #pragma unroll
    for (int mi = 0; mi < 2; mi++)
        #pragma unroll
        for (int nt = 0; nt < 8; nt++)
            #pragma unroll
            for (int e = 0; e < 4; e++) acc[mi][nt][e] = 0.f;

    gemm_mainloop(smem_u32(dyn), Ag, Bg, acc);

    #pragma unroll
    for (int mi = 0; mi < 2; mi++) {
        int row = mbase + wm * 32 + mi * 16 + g;
        #pragma unroll
        for (int nt = 0; nt < 8; nt++) {
            int col = nbase + wn * 64 + nt * 8 + 2 * tg;
            int sel = col >> 9, ci = col & 511;
            const float* bias = (sel == 0) ? bq : (sel == 1) ? bk : bv;
            float b0f = bias[ci], b1f = bias[ci + 1];
            *reinterpret_cast<uint32_t*>(g_qkv + (size_t)row * N_QKV + col) =
                pack_bf16(acc[mi][nt][0] + b0f, acc[mi][nt][1] + b1f);
            *reinterpret_cast<uint32_t*>(g_qkv + (size_t)(row + 8) * N_QKV + col) =
                pack_bf16(acc[mi][nt][2] + b0f, acc[mi][nt][3] + b1f);
        }
    }
}

// ---------------- K3: output projection + bias + residual (inverse roll scatter) ----------------
__global__ __launch_bounds__(512, 1) void proj_kernel(const float* __restrict__ x,
                                                      const float* __restrict__ bo,
                                                      float* __restrict__ out) {
    extern __shared__ char dyn[];
    const int tid = threadIdx.x, lane = tid & 31, warp = tid >> 5;
    const int g = lane >> 2, tg = lane & 3;
    const int wm = warp >> 2, wn = warp & 3;
    const int mbase = blockIdx.y * 128, nbase = blockIdx.x * 256;

    const __nv_bfloat16* Ag = g_o + (size_t)mbase * C_;
    const __nv_bfloat16* Bg = g_woT + (size_t)nbase * C_;

    float acc[2][8][4];
    #pragma unroll
    for (int mi = 0; mi < 2; mi++)
        #pragma unroll
        for (int nt = 0; nt < 8; nt++)
            #pragma unroll
            for (int e = 0; e < 4; e++) acc[mi][nt][e] = 0.f;

    gemm_mainloop(smem_u32(dyn), Ag, Bg, acc);

    #pragma unroll
    for (int mi = 0; mi < 2; mi++) {
        #pragma unroll
        for (int half = 0; half < 2; half++) {
            int row = mbase + wm * 32 + mi * 16 + g + half * 8;
            int win = row >> 6, t = row & 63;
            int b = win >> 6, wh = (win >> 3) & 7, ww = win & 7;
            int i = t >> 3, j = t & 7;
            int r  = (wh * 8 + i + 4) & 63;
            int cc = (ww * 8 + j + 4) & 63;
            size_t off = (size_t)((b * 64 + r) * 64 + cc) * C_;
            #pragma unroll
            for (int nt = 0; nt < 8; nt++) {
                int col = nbase + wn * 64 + nt * 8 + 2 * tg;
                float2 xr = *reinterpret_cast<const float2*>(x + off + col);
                float2 o;
                o.x = acc[mi][nt][2 * half + 0] + bo[col]     + xr.x;
                o.y = acc[mi][nt][2 * half + 1] + bo[col + 1] + xr.y;
                *reinterpret_cast<float2*>(out + off + col) = o;
            }
        }
    }
}

// ---------------- K2: attention per (window, head) ----------------
__global__ __launch_bounds__(128) void attn_kernel() {
    __shared__ __nv_bfloat16 Qs[64 * 72];
    __shared__ __nv_bfloat16 Ks[64 * 72];
    __shared__ __nv_bfloat16 Vs[64 * 72];

    const int nh = blockIdx.x;
    const int n = nh >> 3, h = nh & 7;
    const int tid = threadIdx.x, lane = tid & 31, warp = tid >> 5;
    const int g = lane >> 2, tg = lane & 3;

    const __nv_bfloat16* src = g_qkv + (size_t)(n * 64) * N_QKV + h * 64;
    const uint32_t qS = smem_u32(Qs), kS = smem_u32(Ks), vS = smem_u32(Vs);
    #pragma unroll
    for (int e = 0; e < 4; e++) {
        int it = tid + e * 128;
        int row = it >> 3, seg = it & 7;
        const __nv_bfloat16* rp = src + (size_t)row * N_QKV + seg * 8;
        cp16(qS + row * 144 + seg * 16, rp);
        cp16(kS + row * 144 + seg * 16, rp + 512);
        cp16(vS + row * 144 + seg * 16, rp + 1024);
    }
    cp_commit();
    cp_wait<0>();
    __syncthreads();

    const uint32_t qB = qS + (warp * 16 + (lane & 15)) * 144 + ((lane >> 4) << 4);
    const uint32_t kB = kS + ((((lane >> 4) & 1) * 8 + (lane & 7)) * 144) + (((lane >> 3) & 1) << 4);
    const uint32_t vB = vS + (((lane & 7) + ((lane >> 3) & 1) * 8) * 144) + (((lane >> 4) & 1) << 4);

    float sc[8][4];
    #pragma unroll
    for (int nt = 0; nt < 8; nt++) { sc[nt][0]=0.f; sc[nt][1]=0.f; sc[nt][2]=0.f; sc[nt][3]=0.f; }
    #pragma unroll
    for (int ks = 0; ks < 4; ks++) {
        uint32_t a[4], bb[4][4];
        ldsm4(a, qB + ks * 32);
        #pragma unroll
        for (int p = 0; p < 4; p++)
            ldsm4(bb[p], kB + (p * 16) * 144 + ks * 32);
        #pragma unroll
        for (int nt = 0; nt < 8; nt++)
            mma16816(sc[nt], a[0], a[1], a[2], a[3],
                     bb[nt >> 1][(nt & 1) * 2], bb[nt >> 1][(nt & 1) * 2 + 1]);
    }

    float mx0 = -1e30f, mx1 = -1e30f;
    #pragma unroll
    for (int nt = 0; nt < 8; nt++) {
        mx0 = fmaxf(mx0, fmaxf(sc[nt][0], sc[nt][1]));
        mx1 = fmaxf(mx1, fmaxf(sc[nt][2], sc[nt][3]));
    }
    mx0 = fmaxf(mx0, __shfl_xor_sync(0xffffffff, mx0, 1));
    mx0 = fmaxf(mx0, __shfl_xor_sync(0xffffffff, mx0, 2));
    mx1 = fmaxf(mx1, __shfl_xor_sync(0xffffffff, mx1, 1));
    mx1 = fmaxf(mx1, __shfl_xor_sync(0xffffffff, mx1, 2));
    float s0 = 0.f, s1 = 0.f;
    #pragma unroll
    for (int nt = 0; nt < 8; nt++) {
        sc[nt][0] = __expf((sc[nt][0] - mx0) * SCALE_);
        sc[nt][1] = __expf((sc[nt][1] - mx0) * SCALE_);
        sc[nt][2] = __expf((sc[nt][2] - mx1) * SCALE_);
        sc[nt][3] = __expf((sc[nt][3] - mx1) * SCALE_);
        s0 += sc[nt][0] + sc[nt][1];
        s1 += sc[nt][2] + sc[nt][3];
    }
    s0 += __shfl_xor_sync(0xffffffff, s0, 1);
    s0 += __shfl_xor_sync(0xffffffff, s0, 2);
    s1 += __shfl_xor_sync(0xffffffff, s1, 1);
    s1 += __shfl_xor_sync(0xffffffff, s1, 2);
    const float i0 = 1.f / s0, i1 = 1.f / s1;

    uint32_t pa[8][2];
    #pragma unroll
    for (int nt = 0; nt < 8; nt++) {
        pa[nt][0] = pack_bf16(sc[nt][0] * i0, sc[nt][1] * i0);
        pa[nt][1] = pack_bf16(sc[nt][2] * i1, sc[nt][3] * i1);
    }

    float oc[8][4];
    #pragma unroll
    for (int nt = 0; nt < 8; nt++) { oc[nt][0]=0.f; oc[nt][1]=0.f; oc[nt][2]=0.f; oc[nt][3]=0.f; }
    #pragma unroll
    for (int ks = 0; ks < 4; ks++) {
        uint32_t bb[4][4];
        #pragma unroll
        for (int p = 0; p < 4; p++)
            ldsm4t(bb[p], vB + (ks * 16) * 144 + p * 32);
        uint32_t a0 = pa[2 * ks][0], a1 = pa[2 * ks][1];
        uint32_t a2 = pa[2 * ks + 1][0], a3 = pa[2 * ks + 1][1];
        #pragma unroll
        for (int nt = 0; nt < 8; nt++)
            mma16816(oc[nt], a0, a1, a2, a3,
                     bb[nt >> 1][(nt & 1) * 2], bb[nt >> 1][(nt & 1) * 2 + 1]);
    }

    const int r0 = warp * 16 + g;
    __nv_bfloat16* dst = g_o + (size_t)(n * 64) * C_ + h * 64;
    #pragma unroll
    for (int nt = 0; nt < 8; nt++) {
        int dcol = nt * 8 + 2 * tg;
        *reinterpret_cast<uint32_t*>(dst + (size_t)r0 * C_ + dcol)       = pack_bf16(oc[nt][0], oc[nt][1]);
        *reinterpret_cast<uint32_t*>(dst + (size_t)(r0 + 8) * C_ + dcol) = pack_bf16(oc[nt][2], oc[nt][3]);
    }
}

// ---------------- launch ----------------
extern "C" void kernel_launch(void* const* d_in, const int* in_sizes, int n_in,
                              void* d_out, int out_size) {
    const float* x  = (const float*)d_in[0];
    const float* wq = (const float*)d_in[1];
    const float* bq = (const float*)d_in[2];
    const float* wk = (const float*)d_in[3];
    const float* bk = (const float*)d_in[4];
    const float* wv = (const float*)d_in[5];
    const float* bv = (const float*)d_in[6];
    const float* wo = (const float*)d_in[7];
    const float* bo = (const float*)d_in[8];
    float* out = (float*)d_out;

    cudaFuncSetAttribute(qkv_kernel,  cudaFuncAttributeMaxDynamicSharedMemorySize, SMEM_DYN);
    cudaFuncSetAttribute(proj_kernel, cudaFuncAttributeMaxDynamicSharedMemorySize, SMEM_DYN);

    prep_kernel<<<17408, 256>>>(x, wq, wk, wv, wo);
    dim3 g1(6, 256);
    qkv_kernel<<<g1, 512, SMEM_DYN>>>(bq, bk, bv);
    attn_kernel<<<NWIN * NH_, 128>>>();
    dim3 g3(2, 256);
    proj_kernel<<<g3, 512, SMEM_DYN>>>(x, bo, out);
}

// round 12
// speedup vs baseline: 1.2709x; 1.2709x over previous
#include <cuda_runtime.h>
#include <cuda_bf16.h>
#include <stdint.h>

#define NWIN   512
#define T_     64
#define C_     512
#define NH_    8
#define D_     64
#define MROWS  32768        // NWIN * T_
#define N_QKV  1536
#define SCALE_ 0.125f

// ---------------- scratch ----------------
// g_xw, g_wT, g_o, g_woT are TILED+SWIZZLED: [rowblk][kchunk] 16KB tiles of
// 128 rows x 128B, 16B-chunks permuted by (row&7) (SW128 pattern).
__device__ __nv_bfloat16 g_xw [MROWS * C_];
__device__ __nv_bfloat16 g_qkv[MROWS * N_QKV];   // row-major (attn consumes)
__device__ __nv_bfloat16 g_o  [MROWS * C_];
__device__ __nv_bfloat16 g_wT [N_QKV * C_];
__device__ __nv_bfloat16 g_woT[C_ * C_];

// ---------------- asm helpers ----------------
__device__ __forceinline__ void mma16816(float* c, uint32_t a0, uint32_t a1, uint32_t a2, uint32_t a3,
                                         uint32_t b0, uint32_t b1) {
    asm volatile(
        "mma.sync.aligned.m16n8k16.row.col.f32.bf16.bf16.f32 "
        "{%0,%1,%2,%3}, {%4,%5,%6,%7}, {%8,%9}, {%0,%1,%2,%3};"
        : "+f"(c[0]), "+f"(c[1]), "+f"(c[2]), "+f"(c[3])
        : "r"(a0), "r"(a1), "r"(a2), "r"(a3), "r"(b0), "r"(b1));
}
__device__ __forceinline__ void ldsm4(uint32_t* r, uint32_t addr) {
    asm volatile("ldmatrix.sync.aligned.m8n8.x4.shared.b16 {%0,%1,%2,%3}, [%4];"
                 : "=r"(r[0]), "=r"(r[1]), "=r"(r[2]), "=r"(r[3]) : "r"(addr));
}
__device__ __forceinline__ void ldsm4t(uint32_t* r, uint32_t addr) {
    asm volatile("ldmatrix.sync.aligned.m8n8.x4.trans.shared.b16 {%0,%1,%2,%3}, [%4];"
                 : "=r"(r[0]), "=r"(r[1]), "=r"(r[2]), "=r"(r[3]) : "r"(addr));
}
__device__ __forceinline__ void cp16(uint32_t smem_dst, const void* gmem_src) {
    asm volatile("cp.async.cg.shared.global [%0], [%1], 16;" :: "r"(smem_dst), "l"(gmem_src));
}
__device__ __forceinline__ void cp_commit() { asm volatile("cp.async.commit_group;"); }
template<int N> __device__ __forceinline__ void cp_wait() { asm volatile("cp.async.wait_group %0;" :: "n"(N)); }
__device__ __forceinline__ uint32_t smem_u32(const void* p) {
    return (uint32_t)__cvta_generic_to_shared(p);
}
__device__ __forceinline__ uint32_t pack_bf16(float a, float b) {
    __nv_bfloat162 t = __floats2bfloat162_rn(a, b);
    return *reinterpret_cast<uint32_t*>(&t);
}
// non-tensor bulk async copy gmem->smem with mbarrier completion (sm_90 PTX)
__device__ __forceinline__ void cpbulk(uint32_t dst, const void* src, uint32_t bytes, uint32_t mbar) {
    asm volatile("cp.async.bulk.shared::cta.global.mbarrier::complete_tx::bytes [%0], [%1], %2, [%3];"
                 :: "r"(dst), "l"(src), "r"(bytes), "r"(mbar) : "memory");
}
#define MBARRIER_INIT(mbar, count) \
    asm volatile("mbarrier.init.shared.b64 [%0], %1;" :: "r"((uint32_t)(mbar)), "r"((uint32_t)(count)) : "memory")
#define MBARRIER_EXPECT_TX(mbar, tx) \
    asm volatile("mbarrier.arrive.expect_tx.shared.b64 _, [%0], %1;" :: "r"((uint32_t)(mbar)), "r"((uint32_t)(tx)) : "memory")
#define MBARRIER_WAIT_PARITY(mbar, parity) do { \
    uint32_t _mbar = (uint32_t)(mbar); \
    uint32_t _parity = (uint32_t)(parity); \
    uint32_t _done; \
    asm volatile( \
        "{\n\t.reg .pred p;\n\t" \
        "mbarrier.try_wait.parity.acquire.cta.shared::cta.b64 p, [%1], %2;\n\t" \
        "selp.b32 %0, 1, 0, p;\n\t}" \
        : "=r"(_done) : "r"(_mbar), "r"(_parity) : "memory"); \
    if (!_done) { \
        asm volatile( \
            "{\n\t.reg .pred P1;\n\t" \
            "WAIT_LOOP_%=:\n\t" \
            "mbarrier.try_wait.parity.acquire.cta.shared::cta.b64 P1, [%0], %1, 0x989680;\n\t" \
            "@P1 bra.uni WAIT_DONE_%=;\n\t" \
            "bra.uni WAIT_LOOP_%=;\n\t" \
            "WAIT_DONE_%=:\n\t}" \
            :: "r"(_mbar), "r"(_parity) : "memory"); \
    } \
} while(0)

// ---------------- K0: fused prep — gather x + convert/transpose/tile weights ----------------
// blocks [0,8192): x gather -> g_xw tiled+swizzled
// blocks [8192,8576): wq/wk/wv -> g_wT tiled+swizzled
// blocks [8576,8704): wo -> g_woT tiled+swizzled
__global__ __launch_bounds__(256) void prep_kernel(const float* __restrict__ x,
                                                   const float* __restrict__ wq,
                                                   const float* __restrict__ wk,
                                                   const float* __restrict__ wv,
                                                   const float* __restrict__ wo) {
    int bid = blockIdx.x;
    if (bid < 8192) {
        int idx = bid * 256 + threadIdx.x;        // 0..2097151
        int gr = idx >> 6, u = idx & 63;          // gr: token row, u: 8-elem unit
        int win = gr >> 6, t = gr & 63;
        int b = win >> 6, wh = (win >> 3) & 7, ww = win & 7;
        int i = t >> 3, j = t & 7;
        int r  = (wh * 8 + i + 4) & 63;
        int cc = (ww * 8 + j + 4) & 63;
        const float* src = x + (((b * 64 + r) * 64 + cc) << 9) + u * 8;
        float4 f0 = *reinterpret_cast<const float4*>(src);
        float4 f1 = *reinterpret_cast<const float4*>(src + 4);
        uint4 o;
        o.x = pack_bf16(f0.x, f0.y); o.y = pack_bf16(f0.z, f0.w);
        o.z = pack_bf16(f1.x, f1.y); o.w = pack_bf16(f1.z, f1.w);
        int kc = u >> 3, c = u & 7, trow = gr & 127;
        size_t e = (size_t)((gr >> 7) * 8 + kc) * 8192 + trow * 64 + ((c ^ (trow & 7)) << 3);
        *reinterpret_cast<uint4*>(g_xw + e) = o;
    } else if (bid < 8576) {
        int idx = (bid - 8192) * 256 + threadIdx.x;  // 0..98303
        int jcol = idx >> 6, u = idx & 63;
        int sel = jcol >> 9, jj = jcol & 511;
        const float* w = (sel == 0) ? wq : (sel == 1) ? wk : wv;
        float v[8];
        #pragma unroll
        for (int kk = 0; kk < 8; kk++) v[kk] = w[(u * 8 + kk) * 512 + jj];
        uint4 o;
        o.x = pack_bf16(v[0], v[1]); o.y = pack_bf16(v[2], v[3]);
        o.z = pack_bf16(v[4], v[5]); o.w = pack_bf16(v[6], v[7]);
        int kc = u >> 3, c = u & 7, trow = jcol & 127;
        size_t e = (size_t)((jcol >> 7) * 8 + kc) * 8192 + trow * 64 + ((c ^ (trow & 7)) << 3);
        *reinterpret_cast<uint4*>(g_wT + e) = o;
    } else {
        int idx = (bid - 8576) * 256 + threadIdx.x;  // 0..32767
        int jcol = idx >> 6, u = idx & 63;
        float v[8];
        #pragma unroll
        for (int kk = 0; kk < 8; kk++) v[kk] = wo[(u * 8 + kk) * 512 + jcol];
        uint4 o;
        o.x = pack_bf16(v[0], v[1]); o.y = pack_bf16(v[2], v[3]);
        o.z = pack_bf16(v[4], v[5]); o.w = pack_bf16(v[6], v[7]);
        int kc = u >> 3, c = u & 7, trow = jcol & 127;
        size_t e = (size_t)((jcol >> 7) * 8 + kc) * 8192 + trow * 64 + ((c ^ (trow & 7)) << 3);
        *reinterpret_cast<uint4*>(g_woT + e) = o;
    }
}

// ---------------- GEMM: BM=128, BN=128, BK=64, S=3 bulk-copy stages, 256 threads ----------------
#define NCHUNK_     8
#define STAGE_BYTES 32768
#define SMEM_DYN    (128 + 128 + 3 * STAGE_BYTES)   // align slack + mbar hdr + stages

// mainloop: per chunk, one elected thread issues 2 bulk copies (A,B tiles of 16KB)
// tracked by per-stage mbarriers. acc[2][8][4] per thread (warp tile 32x64, warps 4x2).
__device__ __forceinline__ void gemm_mainloop(uint32_t dynbase,
                                              const char* Abase, const char* Bbase,
                                              float acc[2][8][4]) {
    const int tid = threadIdx.x, lane = tid & 31, warp = tid >> 5;
    const int wm = warp >> 1, wn = warp & 1;     // 4 x 2

    const uint32_t dsm = (dynbase + 127) & ~127u;      // 128B aligned header
    const uint32_t stg0 = dsm + 128;

    if (tid == 0) {
        MBARRIER_INIT(dsm + 0, 1);
        MBARRIER_INIT(dsm + 8, 1);
        MBARRIER_INIT(dsm + 16, 1);
    }
    __syncthreads();

    // prologue: chunks 0,1 -> stages 0,1
    if (tid == 0) {
        MBARRIER_EXPECT_TX(dsm + 0, 2 * 16384);
        cpbulk(stg0, Abase, 16384, dsm + 0);
        cpbulk(stg0 + 16384, Bbase, 16384, dsm + 0);
        MBARRIER_EXPECT_TX(dsm + 8, 2 * 16384);
        cpbulk(stg0 + STAGE_BYTES, Abase + 16384, 16384, dsm + 8);
        cpbulk(stg0 + STAGE_BYTES + 16384, Bbase + 16384, 16384, dsm + 8);
    }

    // per-lane fragment geometry (SW128: 16B chunk index XOR (row&7))
    const int rowA = wm * 32 + (lane & 15);
    const uint32_t aRow = (uint32_t)rowA * 128;
    const int hiA = lane >> 4, swzA = rowA & 7;
    const int rowB = wn * 64 + ((lane >> 4) & 1) * 8 + (lane & 7);
    const uint32_t bRow = (uint32_t)rowB * 128;
    const int hiB = (lane >> 3) & 1, swzB = rowB & 7;

    for (int kc = 0; kc < NCHUNK_; kc++) {
        const int s = kc % 3;
        const uint32_t ph = (uint32_t)((kc / 3) & 1);
        MBARRIER_WAIT_PARITY(dsm + s * 8, ph);

        const uint32_t sA = stg0 + s * STAGE_BYTES;
        const uint32_t sB = sA + 16384;
        #pragma unroll
        for (int ks = 0; ks < 4; ks++) {
            const uint32_t colA = (uint32_t)(((2 * ks + hiA) ^ swzA) << 4);
            const uint32_t colB = (uint32_t)(((2 * ks + hiB) ^ swzB) << 4);
            uint32_t a[2][4], bb[4][4];
            #pragma unroll
            for (int mi = 0; mi < 2; mi++)
                ldsm4(a[mi], sA + aRow + mi * 2048 + colA);
            #pragma unroll
            for (int p = 0; p < 4; p++)
                ldsm4(bb[p], sB + bRow + p * 2048 + colB);
            #pragma unroll
            for (int mi = 0; mi < 2; mi++)
                #pragma unroll
                for (int nt = 0; nt < 8; nt++)
                    mma16816(acc[mi][nt], a[mi][0], a[mi][1], a[mi][2], a[mi][3],
                             bb[nt >> 1][(nt & 1) * 2], bb[nt >> 1][(nt & 1) * 2 + 1]);
        }
        __syncthreads();    // all warps done reading stage s (and stage (kc+2)%3 freed at kc-1)
        if (kc < NCHUNK_ - 2 && tid == 0) {
            const int kn = kc + 2, sn = kn % 3;
            MBARRIER_EXPECT_TX(dsm + sn * 8, 2 * 16384);
            cpbulk(stg0 + sn * STAGE_BYTES, Abase + kn * 16384, 16384, dsm + sn * 8);
            cpbulk(stg0 + sn * STAGE_BYTES + 16384, Bbase + kn * 16384, 16384, dsm + sn * 8);
        }
    }
}

// ---------------- K1: QKV GEMM  [32768,512] x [512,1536] ----------------
__global__ __launch_bounds__(256, 2) void qkv_kernel(const float* __restrict__ bq,
                                                     const float* __restrict__ bk,
                                                     const float* __restrict__ bv) {
    extern __shared__ char dyn[];
    const int tid = threadIdx.x, lane = tid & 31, warp = tid >> 5;
    const int g = lane >> 2, tg = lane & 3;
    const int wm = warp >> 1, wn = warp & 1;
    const int mbase = blockIdx.y * 128, nbase = blockIdx.x * 128;

    const char* Abase = (const char*)g_xw + (size_t)blockIdx.y * 131072;
    const char* Bbase = (const char*)g_wT + (size_t)blockIdx.x * 131072;

    float acc[2][8][4];
    #pragma unroll
    for (int mi = 0; mi < 2; mi++)
        #pragma unroll
        for (int nt = 0; nt < 8; nt++)
            #pragma unroll
            for (int e = 0; e < 4; e++) acc[mi][nt][e] = 0.f;

    gemm_mainloop(smem_u32(dyn), Abase, Bbase, acc);

    #pragma unroll
    for (int mi = 0; mi < 2; mi++) {
        int row = mbase + wm * 32 + mi * 16 + g;
        #pragma unroll
        for (int nt = 0; nt < 8; nt++) {
            int col = nbase + wn * 64 + nt * 8 + 2 * tg;
            int sel = col >> 9, ci = col & 511;
            const float* bias = (sel == 0) ? bq : (sel == 1) ? bk : bv;
            float b0f = bias[ci], b1f = bias[ci + 1];
            *reinterpret_cast<uint32_t*>(g_qkv + (size_t)row * N_QKV + col) =
                pack_bf16(acc[mi][nt][0] + b0f, acc[mi][nt][1] + b1f);
            *reinterpret_cast<uint32_t*>(g_qkv + (size_t)(row + 8) * N_QKV + col) =
                pack_bf16(acc[mi][nt][2] + b0f, acc[mi][nt][3] + b1f);
        }
    }
}

// ---------------- K3: output projection + bias + residual (inverse roll scatter) ----------------
__global__ __launch_bounds__(256, 2) void proj_kernel(const float* __restrict__ x,
                                                      const float* __restrict__ bo,
                                                      float* __restrict__ out) {
    extern __shared__ char dyn[];
    const int tid = threadIdx.x, lane = tid & 31, warp = tid >> 5;
    const int g = lane >> 2, tg = lane & 3;
    const int wm = warp >> 1, wn = warp & 1;
    const int mbase = blockIdx.y * 128, nbase = blockIdx.x * 128;

    const char* Abase = (const char*)g_o + (size_t)blockIdx.y * 131072;
    const char* Bbase = (const char*)g_woT + (size_t)blockIdx.x * 131072;

    float acc[2][8][4];
    #pragma unroll
    for (int mi = 0; mi < 2; mi++)
        #pragma unroll
        for (int nt = 0; nt < 8; nt++)
            #pragma unroll
            for (int e = 0; e < 4; e++) acc[mi][nt][e] = 0.f;

    gemm_mainloop(smem_u32(dyn), Abase, Bbase, acc);

    #pragma unroll
    for (int mi = 0; mi < 2; mi++) {
        #pragma unroll
        for (int half = 0; half < 2; half++) {
            int row = mbase + wm * 32 + mi * 16 + g + half * 8;
            int win = row >> 6, t = row & 63;
            int b = win >> 6, wh = (win >> 3) & 7, ww = win & 7;
            int i = t >> 3, j = t & 7;
            int r  = (wh * 8 + i + 4) & 63;
            int cc = (ww * 8 + j + 4) & 63;
            size_t off = (size_t)((b * 64 + r) * 64 + cc) * C_;
            #pragma unroll
            for (int nt = 0; nt < 8; nt++) {
                int col = nbase + wn * 64 + nt * 8 + 2 * tg;
                float2 xr = *reinterpret_cast<const float2*>(x + off + col);
                float2 o;
                o.x = acc[mi][nt][2 * half + 0] + bo[col]     + xr.x;
                o.y = acc[mi][nt][2 * half + 1] + bo[col + 1] + xr.y;
                *reinterpret_cast<float2*>(out + off + col) = o;
            }
        }
    }
}

// ---------------- K2: attention per (window, head) ----------------
__global__ __launch_bounds__(128) void attn_kernel() {
    __shared__ __nv_bfloat16 Qs[64 * 72];
    __shared__ __nv_bfloat16 Ks[64 * 72];
    __shared__ __nv_bfloat16 Vs[64 * 72];

    const int nh = blockIdx.x;
    const int n = nh >> 3, h = nh & 7;
    const int tid = threadIdx.x, lane = tid & 31, warp = tid >> 5;
    const int g = lane >> 2, tg = lane & 3;

    const __nv_bfloat16* src = g_qkv + (size_t)(n * 64) * N_QKV + h * 64;
    const uint32_t qS = smem_u32(Qs), kS = smem_u32(Ks), vS = smem_u32(Vs);
    #pragma unroll
    for (int e = 0; e < 4; e++) {
        int it = tid + e * 128;
        int row = it >> 3, seg = it & 7;
        const __nv_bfloat16* rp = src + (size_t)row * N_QKV + seg * 8;
        cp16(qS + row * 144 + seg * 16, rp);
        cp16(kS + row * 144 + seg * 16, rp + 512);
        cp16(vS + row * 144 + seg * 16, rp + 1024);
    }
    cp_commit();
    cp_wait<0>();
    __syncthreads();

    const uint32_t qB = qS + (warp * 16 + (lane & 15)) * 144 + ((lane >> 4) << 4);
    const uint32_t kB = kS + ((((lane >> 4) & 1) * 8 + (lane & 7)) * 144) + (((lane >> 3) & 1) << 4);
    const uint32_t vB = vS + (((lane & 7) + ((lane >> 3) & 1) * 8) * 144) + (((lane >> 4) & 1) << 4);

    float sc[8][4];
    #pragma unroll
    for (int nt = 0; nt < 8; nt++) { sc[nt][0]=0.f; sc[nt][1]=0.f; sc[nt][2]=0.f; sc[nt][3]=0.f; }
    #pragma unroll
    for (int ks = 0; ks < 4; ks++) {
        uint32_t a[4], bb[4][4];
        ldsm4(a, qB + ks * 32);
        #pragma unroll
        for (int p = 0; p < 4; p++)
            ldsm4(bb[p], kB + (p * 16) * 144 + ks * 32);
        #pragma unroll
        for (int nt = 0; nt < 8; nt++)
            mma16816(sc[nt], a[0], a[1], a[2], a[3],
                     bb[nt >> 1][(nt & 1) * 2], bb[nt >> 1][(nt & 1) * 2 + 1]);
    }

    float mx0 = -1e30f, mx1 = -1e30f;
    #pragma unroll
    for (int nt = 0; nt < 8; nt++) {
        mx0 = fmaxf(mx0, fmaxf(sc[nt][0], sc[nt][1]));
        mx1 = fmaxf(mx1, fmaxf(sc[nt][2], sc[nt][3]));
    }
    mx0 = fmaxf(mx0, __shfl_xor_sync(0xffffffff, mx0, 1));
    mx0 = fmaxf(mx0, __shfl_xor_sync(0xffffffff, mx0, 2));
    mx1 = fmaxf(mx1, __shfl_xor_sync(0xffffffff, mx1, 1));
    mx1 = fmaxf(mx1, __shfl_xor_sync(0xffffffff, mx1, 2));
    float s0 = 0.f, s1 = 0.f;
    #pragma unroll
    for (int nt = 0; nt < 8; nt++) {
        sc[nt][0] = __expf((sc[nt][0] - mx0) * SCALE_);
        sc[nt][1] = __expf((sc[nt][1] - mx0) * SCALE_);
        sc[nt][2] = __expf((sc[nt][2] - mx1) * SCALE_);
        sc[nt][3] = __expf((sc[nt][3] - mx1) * SCALE_);
        s0 += sc[nt][0] + sc[nt][1];
        s1 += sc[nt][2] + sc[nt][3];
    }
    s0 += __shfl_xor_sync(0xffffffff, s0, 1);
    s0 += __shfl_xor_sync(0xffffffff, s0, 2);
    s1 += __shfl_xor_sync(0xffffffff, s1, 1);
    s1 += __shfl_xor_sync(0xffffffff, s1, 2);
    const float i0 = 1.f / s0, i1 = 1.f / s1;

    uint32_t pa[8][2];
    #pragma unroll
    for (int nt = 0; nt < 8; nt++) {
        pa[nt][0] = pack_bf16(sc[nt][0] * i0, sc[nt][1] * i0);
        pa[nt][1] = pack_bf16(sc[nt][2] * i1, sc[nt][3] * i1);
    }

    float oc[8][4];
    #pragma unroll
    for (int nt = 0; nt < 8; nt++) { oc[nt][0]=0.f; oc[nt][1]=0.f; oc[nt][2]=0.f; oc[nt][3]=0.f; }
    #pragma unroll
    for (int ks = 0; ks < 4; ks++) {
        uint32_t bb[4][4];
        #pragma unroll
        for (int p = 0; p < 4; p++)
            ldsm4t(bb[p], vB + (ks * 16) * 144 + p * 32);
        uint32_t a0 = pa[2 * ks][0], a1 = pa[2 * ks][1];
        uint32_t a2 = pa[2 * ks + 1][0], a3 = pa[2 * ks + 1][1];
        #pragma unroll
        for (int nt = 0; nt < 8; nt++)
            mma16816(oc[nt], a0, a1, a2, a3,
                     bb[nt >> 1][(nt & 1) * 2], bb[nt >> 1][(nt & 1) * 2 + 1]);
    }

    // store to g_o TILED+SWIZZLED: tile = (n>>1)*8 + h, trow = (n&1)*64 + t
    const int r0 = warp * 16 + g;
    const size_t tbase = (size_t)((n >> 1) * 8 + h) * 8192;
    #pragma unroll
    for (int nt = 0; nt < 8; nt++) {
        int dcol = nt * 8 + 2 * tg;           // chunk = nt, off = 2*tg
        int trow0 = (n & 1) * 64 + r0;
        int trow1 = trow0 + 8;
        size_t e0 = tbase + trow0 * 64 + ((nt ^ (trow0 & 7)) << 3) + 2 * tg;
        size_t e1 = tbase + trow1 * 64 + ((nt ^ (trow1 & 7)) << 3) + 2 * tg;
        *reinterpret_cast<uint32_t*>(g_o + e0) = pack_bf16(oc[nt][0], oc[nt][1]);
        *reinterpret_cast<uint32_t*>(g_o + e1) = pack_bf16(oc[nt][2], oc[nt][3]);
    }
}

// ---------------- launch ----------------
extern "C" void kernel_launch(void* const* d_in, const int* in_sizes, int n_in,
                              void* d_out, int out_size) {
    const float* x  = (const float*)d_in[0];
    const float* wq = (const float*)d_in[1];
    const float* bq = (const float*)d_in[2];
    const float* wk = (const float*)d_in[3];
    const float* bk = (const float*)d_in[4];
    const float* wv = (const float*)d_in[5];
    const float* bv = (const float*)d_in[6];
    const float* wo = (const float*)d_in[7];
    const float* bo = (const float*)d_in[8];
    float* out = (float*)d_out;

    cudaFuncSetAttribute(qkv_kernel,  cudaFuncAttributeMaxDynamicSharedMemorySize, SMEM_DYN);
    cudaFuncSetAttribute(proj_kernel, cudaFuncAttributeMaxDynamicSharedMemorySize, SMEM_DYN);

    prep_kernel<<<8704, 256>>>(x, wq, wk, wv, wo);
    dim3 g1(12, 256);
    qkv_kernel<<<g1, 256, SMEM_DYN>>>(bq, bk, bv);
    attn_kernel<<<NWIN * NH_, 128>>>();
    dim3 g3(4, 256);
    proj_kernel<<<g3, 256, SMEM_DYN>>>(x, bo, out);
}

// round 13
// speedup vs baseline: 1.5316x; 1.2052x over previous
#include <cuda_runtime.h>
#include <cuda_bf16.h>
#include <stdint.h>

#define NWIN   512
#define T_     64
#define C_     512
#define NH_    8
#define D_     64
#define MROWS  32768
#define SCALE_ 0.125f

// ---------------- scratch ----------------
// g_xw: per-window tiles [win 512][kc 16] of 64 rows x 32 bf16 (4KB, R10-swizzled)
// g_wT: per-head tiles   [head 8][kc 16] of 192 rows (q|k|v cols) x 32 bf16 (12KB, R10-swizzled)
// g_o / g_woT: R12 format — [rowblk][kc64] 16KB tiles of 128 rows x 64 bf16, SW128
__device__ __nv_bfloat16 g_xw [MROWS * C_];
__device__ __nv_bfloat16 g_o  [MROWS * C_];
__device__ __nv_bfloat16 g_wT [1536 * C_];
__device__ __nv_bfloat16 g_woT[C_ * C_];

// ---------------- asm helpers ----------------
__device__ __forceinline__ void mma16816(float* c, uint32_t a0, uint32_t a1, uint32_t a2, uint32_t a3,
                                         uint32_t b0, uint32_t b1) {
    asm volatile(
        "mma.sync.aligned.m16n8k16.row.col.f32.bf16.bf16.f32 "
        "{%0,%1,%2,%3}, {%4,%5,%6,%7}, {%8,%9}, {%0,%1,%2,%3};"
        : "+f"(c[0]), "+f"(c[1]), "+f"(c[2]), "+f"(c[3])
        : "r"(a0), "r"(a1), "r"(a2), "r"(a3), "r"(b0), "r"(b1));
}
__device__ __forceinline__ void ldsm4(uint32_t* r, uint32_t addr) {
    asm volatile("ldmatrix.sync.aligned.m8n8.x4.shared.b16 {%0,%1,%2,%3}, [%4];"
                 : "=r"(r[0]), "=r"(r[1]), "=r"(r[2]), "=r"(r[3]) : "r"(addr));
}
__device__ __forceinline__ void ldsm4t(uint32_t* r, uint32_t addr) {
    asm volatile("ldmatrix.sync.aligned.m8n8.x4.trans.shared.b16 {%0,%1,%2,%3}, [%4];"
                 : "=r"(r[0]), "=r"(r[1]), "=r"(r[2]), "=r"(r[3]) : "r"(addr));
}
__device__ __forceinline__ uint32_t smem_u32(const void* p) {
    return (uint32_t)__cvta_generic_to_shared(p);
}
__device__ __forceinline__ uint32_t pack_bf16(float a, float b) {
    __nv_bfloat162 t = __floats2bfloat162_rn(a, b);
    return *reinterpret_cast<uint32_t*>(&t);
}
__device__ __forceinline__ void cpbulk(uint32_t dst, const void* src, uint32_t bytes, uint32_t mbar) {
    asm volatile("cp.async.bulk.shared::cta.global.mbarrier::complete_tx::bytes [%0], [%1], %2, [%3];"
                 :: "r"(dst), "l"(src), "r"(bytes), "r"(mbar) : "memory");
}
#define MBARRIER_INIT(mbar, count) \
    asm volatile("mbarrier.init.shared.b64 [%0], %1;" :: "r"((uint32_t)(mbar)), "r"((uint32_t)(count)) : "memory")
#define MBARRIER_EXPECT_TX(mbar, tx) \
    asm volatile("mbarrier.arrive.expect_tx.shared.b64 _, [%0], %1;" :: "r"((uint32_t)(mbar)), "r"((uint32_t)(tx)) : "memory")
#define MBARRIER_WAIT_PARITY(mbar, parity) do { \
    uint32_t _mbar = (uint32_t)(mbar); \
    uint32_t _parity = (uint32_t)(parity); \
    uint32_t _done; \
    asm volatile( \
        "{\n\t.reg .pred p;\n\t" \
        "mbarrier.try_wait.parity.acquire.cta.shared::cta.b64 p, [%1], %2;\n\t" \
        "selp.b32 %0, 1, 0, p;\n\t}" \
        : "=r"(_done) : "r"(_mbar), "r"(_parity) : "memory"); \
    if (!_done) { \
        asm volatile( \
            "{\n\t.reg .pred P1;\n\t" \
            "WAIT_LOOP_%=:\n\t" \
            "mbarrier.try_wait.parity.acquire.cta.shared::cta.b64 P1, [%0], %1, 0x989680;\n\t" \
            "@P1 bra.uni WAIT_DONE_%=;\n\t" \
            "bra.uni WAIT_LOOP_%=;\n\t" \
            "WAIT_DONE_%=:\n\t}" \
            :: "r"(_mbar), "r"(_parity) : "memory"); \
    } \
} while(0)

// R10 swizzle: byte address of 16B chunk c (0..3) of logical 64B row `row`.
// Conflict-free for ldsm.x4 reads and 16B stores.
__device__ __forceinline__ uint32_t sw_addr(int row, int c) {
    return (uint32_t)(((row >> 1) << 7) + (((((row & 1) << 2) | c) ^ ((row >> 1) & 7)) << 4));
}

// ---------------- K0: prep — gather x, tile weights ----------------
// blocks [0,8192): x -> g_xw (per-window 4KB chunks)
// blocks [8192,8576): wq/wk/wv -> g_wT (per-head 12KB chunks, rows = sel*64+d)
// blocks [8576,8704): wo -> g_woT (R12 16KB/BK64 format)
__global__ __launch_bounds__(256) void prep_kernel(const float* __restrict__ x,
                                                   const float* __restrict__ wq,
                                                   const float* __restrict__ wk,
                                                   const float* __restrict__ wv,
                                                   const float* __restrict__ wo) {
    int bid = blockIdx.x;
    if (bid < 8192) {
        int idx = bid * 256 + threadIdx.x;        // 0..2097151
        int gr = idx >> 6, u = idx & 63;
        int win = gr >> 6, t = gr & 63;
        int b = win >> 6, wh = (win >> 3) & 7, ww = win & 7;
        int i = t >> 3, j = t & 7;
        int r  = (wh * 8 + i + 4) & 63;
        int cc = (ww * 8 + j + 4) & 63;
        const float* src = x + (((b * 64 + r) * 64 + cc) << 9) + u * 8;
        float4 f0 = *reinterpret_cast<const float4*>(src);
        float4 f1 = *reinterpret_cast<const float4*>(src + 4);
        uint4 o;
        o.x = pack_bf16(f0.x, f0.y); o.y = pack_bf16(f0.z, f0.w);
        o.z = pack_bf16(f1.x, f1.y); o.w = pack_bf16(f1.z, f1.w);
        int kc = u >> 2, c = u & 3, trow = gr & 63;
        size_t off = (size_t)(win * 16 + kc) * 4096 + sw_addr(trow, c);
        *reinterpret_cast<uint4*>((char*)g_xw + off) = o;
    } else if (bid < 8576) {
        int idx = (bid - 8192) * 256 + threadIdx.x;  // 0..98303
        int jcol = idx >> 6, u = idx & 63;
        int sel = jcol >> 9, jj = jcol & 511;
        int h = jj >> 6, d = jj & 63;
        const float* w = (sel == 0) ? wq : (sel == 1) ? wk : wv;
        float v[8];
        #pragma unroll
        for (int kk = 0; kk < 8; kk++) v[kk] = w[(u * 8 + kk) * 512 + jj];
        uint4 o;
        o.x = pack_bf16(v[0], v[1]); o.y = pack_bf16(v[2], v[3]);
        o.z = pack_bf16(v[4], v[5]); o.w = pack_bf16(v[6], v[7]);
        int kc = u >> 2, c = u & 3, brow = sel * 64 + d;
        size_t off = (size_t)(h * 16 + kc) * 12288 + sw_addr(brow, c);
        *reinterpret_cast<uint4*>((char*)g_wT + off) = o;
    } else {
        int idx = (bid - 8576) * 256 + threadIdx.x;  // 0..32767
        int jcol = idx >> 6, u = idx & 63;
        float v[8];
        #pragma unroll
        for (int kk = 0; kk < 8; kk++) v[kk] = wo[(u * 8 + kk) * 512 + jcol];
        uint4 o;
        o.x = pack_bf16(v[0], v[1]); o.y = pack_bf16(v[2], v[3]);
        o.z = pack_bf16(v[4], v[5]); o.w = pack_bf16(v[6], v[7]);
        int kc = u >> 3, c = u & 7, trow = jcol & 127;
        size_t e = (size_t)((jcol >> 7) * 8 + kc) * 8192 + trow * 64 + ((c ^ (trow & 7)) << 3);
        *reinterpret_cast<uint4*>(g_woT + e) = o;
    }
}

// ---------------- K1: FUSED qkv GEMM + attention per (head, window) ----------------
// 128 threads, 4 warps 2x2 over 64x192 tile; BK=32, 3 bulk-copy stages.
#define F_STAGE   16384                    // A 4KB + B 12KB
#define F_SMEM    (128 + 3 * F_STAGE + 3 * 8192)   // hdr + stages + Q|K|V (64x128B each)

__global__ __launch_bounds__(128, 3) void qkv_attn_kernel(const float* __restrict__ bq,
                                                          const float* __restrict__ bk,
                                                          const float* __restrict__ bv) {
    extern __shared__ char dyn[];
    const int head = blockIdx.x, win = blockIdx.y;
    const int tid = threadIdx.x, lane = tid & 31, warp = tid >> 5;
    const int wm = warp >> 1, wn = warp & 1;       // 2 x 2
    const int g = lane >> 2, tg = lane & 3;

    const uint32_t dsm = (smem_u32(dyn) + 127) & ~127u;
    const uint32_t stg0 = dsm + 128;
    const uint32_t qkv0 = stg0 + 3 * F_STAGE;      // Qs | Ks(+8192) | Vs(+16384)

    if (tid == 0) {
        MBARRIER_INIT(dsm + 0, 1);
        MBARRIER_INIT(dsm + 8, 1);
        MBARRIER_INIT(dsm + 16, 1);
    }
    __syncthreads();

    const char* Abase = (const char*)g_xw + (size_t)win * 65536;
    const char* Bbase = (const char*)g_wT + (size_t)head * 196608;

    if (tid == 0) {
        MBARRIER_EXPECT_TX(dsm + 0, F_STAGE);
        cpbulk(stg0, Abase, 4096, dsm + 0);
        cpbulk(stg0 + 4096, Bbase, 12288, dsm + 0);
        MBARRIER_EXPECT_TX(dsm + 8, F_STAGE);
        cpbulk(stg0 + F_STAGE, Abase + 4096, 4096, dsm + 8);
        cpbulk(stg0 + F_STAGE + 4096, Bbase + 12288, 12288, dsm + 8);
    }

    float acc[2][12][4];
    #pragma unroll
    for (int mi = 0; mi < 2; mi++)
        #pragma unroll
        for (int nt = 0; nt < 12; nt++)
            #pragma unroll
            for (int e = 0; e < 4; e++) acc[mi][nt][e] = 0.f;

    // fragment geometry (R10 swizzle)
    const int r_a = wm * 32 + (lane & 15);
    const int hiA = lane >> 4;
    const uint32_t aOff0 = sw_addr(r_a, hiA), aOff1 = sw_addr(r_a, hiA + 2);
    const int r_b = wn * 96 + ((lane >> 4) & 1) * 8 + (lane & 7);
    const int hiB = (lane >> 3) & 1;
    const uint32_t bOff0 = sw_addr(r_b, hiB), bOff1 = sw_addr(r_b, hiB + 2);

    for (int kc = 0; kc < 16; kc++) {
        const int s = kc % 3;
        MBARRIER_WAIT_PARITY(dsm + s * 8, (uint32_t)((kc / 3) & 1));
        const uint32_t sA = stg0 + s * F_STAGE;
        const uint32_t sB = sA + 4096;
        #pragma unroll
        for (int ks = 0; ks < 2; ks++) {
            const uint32_t aOff = sA + (ks ? aOff1 : aOff0);
            const uint32_t bOff = sB + (ks ? bOff1 : bOff0);
            uint32_t a[2][4], bb[6][4];
            #pragma unroll
            for (int mi = 0; mi < 2; mi++)
                ldsm4(a[mi], aOff + mi * 1024);
            #pragma unroll
            for (int p = 0; p < 6; p++)
                ldsm4(bb[p], bOff + p * 1024);
            #pragma unroll
            for (int mi = 0; mi < 2; mi++)
                #pragma unroll
                for (int nt = 0; nt < 12; nt++)
                    mma16816(acc[mi][nt], a[mi][0], a[mi][1], a[mi][2], a[mi][3],
                             bb[nt >> 1][(nt & 1) * 2], bb[nt >> 1][(nt & 1) * 2 + 1]);
        }
        __syncthreads();
        if (kc < 14 && tid == 0) {
            const int kn = kc + 2, sn = kn % 3;
            MBARRIER_EXPECT_TX(dsm + sn * 8, F_STAGE);
            cpbulk(stg0 + sn * F_STAGE, Abase + kn * 4096, 4096, dsm + sn * 8);
            cpbulk(stg0 + sn * F_STAGE + 4096, Bbase + (size_t)kn * 12288, 12288, dsm + sn * 8);
        }
    }

    // epilogue: +bias, write Q/K/V into SW128 smem (64 rows x 128B each)
    #pragma unroll
    for (int mi = 0; mi < 2; mi++) {
        #pragma unroll
        for (int nt = 0; nt < 12; nt++) {
            const int col = wn * 96 + nt * 8 + 2 * tg;
            const int sel = col >> 6, d = col & 63;
            const float* bias = (sel == 0) ? bq : (sel == 1) ? bk : bv;
            const float b0f = bias[head * 64 + d], b1f = bias[head * 64 + d + 1];
            const uint32_t base = qkv0 + sel * 8192;
            const int row0 = wm * 32 + mi * 16 + g, row1 = row0 + 8;
            const uint32_t a0 = base + row0 * 128 + ((((d >> 3) ^ (row0 & 7))) << 4) + (d & 7) * 2;
            const uint32_t a1 = base + row1 * 128 + ((((d >> 3) ^ (row1 & 7))) << 4) + (d & 7) * 2;
            uint32_t v0 = pack_bf16(acc[mi][nt][0] + b0f, acc[mi][nt][1] + b1f);
            uint32_t v1 = pack_bf16(acc[mi][nt][2] + b0f, acc[mi][nt][3] + b1f);
            asm volatile("st.shared.b32 [%0], %1;" :: "r"(a0), "r"(v0) : "memory");
            asm volatile("st.shared.b32 [%0], %1;" :: "r"(a1), "r"(v1) : "memory");
        }
    }
    __syncthreads();

    // ---- attention (attn_kernel math, SW128 addressing) ----
    const uint32_t Qs = qkv0, Ks = qkv0 + 8192, Vs = qkv0 + 16384;
    const int qRow = warp * 16 + (lane & 15);
    const int hiQ = lane >> 4, swzQ = qRow & 7;
    const uint32_t qBase = Qs + qRow * 128;
    const int kRow = ((lane >> 4) & 1) * 8 + (lane & 7);
    const int hiK = (lane >> 3) & 1, swzK = kRow & 7;
    const uint32_t kBase = Ks + kRow * 128;
    const int vRow = (lane & 7) + ((lane >> 3) & 1) * 8;
    const int hiV = (lane >> 4) & 1, swzV = vRow & 7;
    const uint32_t vBase = Vs + vRow * 128;

    float sc[8][4];
    #pragma unroll
    for (int nt = 0; nt < 8; nt++) { sc[nt][0]=0.f; sc[nt][1]=0.f; sc[nt][2]=0.f; sc[nt][3]=0.f; }
    #pragma unroll
    for (int ks = 0; ks < 4; ks++) {
        uint32_t a[4], bb[4][4];
        ldsm4(a, qBase + (((ks * 2 + hiQ) ^ swzQ) << 4));
        #pragma unroll
        for (int p = 0; p < 4; p++)
            ldsm4(bb[p], kBase + p * 2048 + (((ks * 2 + hiK) ^ swzK) << 4));
        #pragma unroll
        for (int nt = 0; nt < 8; nt++)
            mma16816(sc[nt], a[0], a[1], a[2], a[3],
                     bb[nt >> 1][(nt & 1) * 2], bb[nt >> 1][(nt & 1) * 2 + 1]);
    }

    float mx0 = -1e30f, mx1 = -1e30f;
    #pragma unroll
    for (int nt = 0; nt < 8; nt++) {
        mx0 = fmaxf(mx0, fmaxf(sc[nt][0], sc[nt][1]));
        mx1 = fmaxf(mx1, fmaxf(sc[nt][2], sc[nt][3]));
    }
    mx0 = fmaxf(mx0, __shfl_xor_sync(0xffffffff, mx0, 1));
    mx0 = fmaxf(mx0, __shfl_xor_sync(0xffffffff, mx0, 2));
    mx1 = fmaxf(mx1, __shfl_xor_sync(0xffffffff, mx1, 1));
    mx1 = fmaxf(mx1, __shfl_xor_sync(0xffffffff, mx1, 2));
    float s0 = 0.f, s1 = 0.f;
    #pragma unroll
    for (int nt = 0; nt < 8; nt++) {
        sc[nt][0] = __expf((sc[nt][0] - mx0) * SCALE_);
        sc[nt][1] = __expf((sc[nt][1] - mx0) * SCALE_);
        sc[nt][2] = __expf((sc[nt][2] - mx1) * SCALE_);
        sc[nt][3] = __expf((sc[nt][3] - mx1) * SCALE_);
        s0 += sc[nt][0] + sc[nt][1];
        s1 += sc[nt][2] + sc[nt][3];
    }
    s0 += __shfl_xor_sync(0xffffffff, s0, 1);
    s0 += __shfl_xor_sync(0xffffffff, s0, 2);
    s1 += __shfl_xor_sync(0xffffffff, s1, 1);
    s1 += __shfl_xor_sync(0xffffffff, s1, 2);
    const float i0 = 1.f / s0, i1 = 1.f / s1;

    uint32_t pa[8][2];
    #pragma unroll
    for (int nt = 0; nt < 8; nt++) {
        pa[nt][0] = pack_bf16(sc[nt][0] * i0, sc[nt][1] * i0);
        pa[nt][1] = pack_bf16(sc[nt][2] * i1, sc[nt][3] * i1);
    }

    float oc[8][4];
    #pragma unroll
    for (int nt = 0; nt < 8; nt++) { oc[nt][0]=0.f; oc[nt][1]=0.f; oc[nt][2]=0.f; oc[nt][3]=0.f; }
    #pragma unroll
    for (int ks = 0; ks < 4; ks++) {
        uint32_t bb[4][4];
        #pragma unroll
        for (int p = 0; p < 4; p++)
            ldsm4t(bb[p], vBase + ks * 2048 + (((p * 2 + hiV) ^ swzV) << 4));
        uint32_t a0 = pa[2 * ks][0], a1 = pa[2 * ks][1];
        uint32_t a2 = pa[2 * ks + 1][0], a3 = pa[2 * ks + 1][1];
        #pragma unroll
        for (int nt = 0; nt < 8; nt++)
            mma16816(oc[nt], a0, a1, a2, a3,
                     bb[nt >> 1][(nt & 1) * 2], bb[nt >> 1][(nt & 1) * 2 + 1]);
    }

    // store g_o in R12 tiled+swizzled format (tile = (win>>1)*8 + head)
    const int r0 = warp * 16 + g;
    const size_t tbase = (size_t)((win >> 1) * 8 + head) * 8192;
    const int trow0 = (win & 1) * 64 + r0;
    #pragma unroll
    for (int nt = 0; nt < 8; nt++) {
        const int trow1 = trow0 + 8;
        size_t e0 = tbase + trow0 * 64 + ((nt ^ (trow0 & 7)) << 3) + 2 * tg;
        size_t e1 = tbase + trow1 * 64 + ((nt ^ (trow1 & 7)) << 3) + 2 * tg;
        *reinterpret_cast<uint32_t*>(g_o + e0) = pack_bf16(oc[nt][0], oc[nt][1]);
        *reinterpret_cast<uint32_t*>(g_o + e1) = pack_bf16(oc[nt][2], oc[nt][3]);
    }
}

// ---------------- proj GEMM (R12, unchanged): BM=128,BN=128,BK=64, bulk 3-stage ----------------
#define NCHUNK_     8
#define STAGE_BYTES 32768
#define SMEM_DYN    (128 + 128 + 3 * STAGE_BYTES)

__device__ __forceinline__ void gemm_mainloop(uint32_t dynbase,
                                              const char* Abase, const char* Bbase,
                                              float acc[2][8][4]) {
    const int tid = threadIdx.x, lane = tid & 31, warp = tid >> 5;
    const int wm = warp >> 1, wn = warp & 1;

    const uint32_t dsm = (dynbase + 127) & ~127u;
    const uint32_t stg0 = dsm + 128;

    if (tid == 0) {
        MBARRIER_INIT(dsm + 0, 1);
        MBARRIER_INIT(dsm + 8, 1);
        MBARRIER_INIT(dsm + 16, 1);
    }
    __syncthreads();

    if (tid == 0) {
        MBARRIER_EXPECT_TX(dsm + 0, 2 * 16384);
        cpbulk(stg0, Abase, 16384, dsm + 0);
        cpbulk(stg0 + 16384, Bbase, 16384, dsm + 0);
        MBARRIER_EXPECT_TX(dsm + 8, 2 * 16384);
        cpbulk(stg0 + STAGE_BYTES, Abase + 16384, 16384, dsm + 8);
        cpbulk(stg0 + STAGE_BYTES + 16384, Bbase + 16384, 16384, dsm + 8);
    }

    const int rowA = wm * 32 + (lane & 15);
    const uint32_t aRow = (uint32_t)rowA * 128;
    const int hiA = lane >> 4, swzA = rowA & 7;
    const int rowB = wn * 64 + ((lane >> 4) & 1) * 8 + (lane & 7);
    const uint32_t bRow = (uint32_t)rowB * 128;
    const int hiB = (lane >> 3) & 1, swzB = rowB & 7;

    for (int kc = 0; kc < NCHUNK_; kc++) {
        const int s = kc % 3;
        MBARRIER_WAIT_PARITY(dsm + s * 8, (uint32_t)((kc / 3) & 1));

        const uint32_t sA = stg0 + s * STAGE_BYTES;
        const uint32_t sB = sA + 16384;
        #pragma unroll
        for (int ks = 0; ks < 4; ks++) {
            const uint32_t colA = (uint32_t)(((2 * ks + hiA) ^ swzA) << 4);
            const uint32_t colB = (uint32_t)(((2 * ks + hiB) ^ swzB) << 4);
            uint32_t a[2][4], bb[4][4];
            #pragma unroll
            for (int mi = 0; mi < 2; mi++)
                ldsm4(a[mi], sA + aRow + mi * 2048 + colA);
            #pragma unroll
            for (int p = 0; p < 4; p++)
                ldsm4(bb[p], sB + bRow + p * 2048 + colB);
            #pragma unroll
            for (int mi = 0; mi < 2; mi++)
                #pragma unroll
                for (int nt = 0; nt < 8; nt++)
                    mma16816(acc[mi][nt], a[mi][0], a[mi][1], a[mi][2], a[mi][3],
                             bb[nt >> 1][(nt & 1) * 2], bb[nt >> 1][(nt & 1) * 2 + 1]);
        }
        __syncthreads();
        if (kc < NCHUNK_ - 2 && tid == 0) {
            const int kn = kc + 2, sn = kn % 3;
            MBARRIER_EXPECT_TX(dsm + sn * 8, 2 * 16384);
            cpbulk(stg0 + sn * STAGE_BYTES, Abase + kn * 16384, 16384, dsm + sn * 8);
            cpbulk(stg0 + sn * STAGE_BYTES + 16384, Bbase + kn * 16384, 16384, dsm + sn * 8);
        }
    }
}

__global__ __launch_bounds__(256, 2) void proj_kernel(const float* __restrict__ x,
                                                      const float* __restrict__ bo,
                                                      float* __restrict__ out) {
    extern __shared__ char dyn[];
    const int tid = threadIdx.x, lane = tid & 31, warp = tid >> 5;
    const int g = lane >> 2, tg = lane & 3;
    const int wm = warp >> 1, wn = warp & 1;
    const int mbase = blockIdx.y * 128, nbase = blockIdx.x * 128;

    const char* Abase = (const char*)g_o + (size_t)blockIdx.y * 131072;
    const char* Bbase = (const char*)g_woT + (size_t)blockIdx.x * 131072;

    float acc[2][8][4];
    #pragma unroll
    for (int mi = 0; mi < 2; mi++)
        #pragma unroll
        for (int nt = 0; nt < 8; nt++)
            #pragma unroll
            for (int e = 0; e < 4; e++) acc[mi][nt][e] = 0.f;

    gemm_mainloop(smem_u32(dyn), Abase, Bbase, acc);

    #pragma unroll
    for (int mi = 0; mi < 2; mi++) {
        #pragma unroll
        for (int half = 0; half < 2; half++) {
            int row = mbase + wm * 32 + mi * 16 + g + half * 8;
            int win = row >> 6, t = row & 63;
            int b = win >> 6, wh = (win >> 3) & 7, ww = win & 7;
            int i = t >> 3, j = t & 7;
            int r  = (wh * 8 + i + 4) & 63;
            int cc = (ww * 8 + j + 4) & 63;
            size_t off = (size_t)((b * 64 + r) * 64 + cc) * C_;
            #pragma unroll
            for (int nt = 0; nt < 8; nt++) {
                int col = nbase + wn * 64 + nt * 8 + 2 * tg;
                float2 xr = *reinterpret_cast<const float2*>(x + off + col);
                float2 o;
                o.x = acc[mi][nt][2 * half + 0] + bo[col]     + xr.x;
                o.y = acc[mi][nt][2 * half + 1] + bo[col + 1] + xr.y;
                *reinterpret_cast<float2*>(out + off + col) = o;
            }
        }
    }
}

// ---------------- launch ----------------
extern "C" void kernel_launch(void* const* d_in, const int* in_sizes, int n_in,
                              void* d_out, int out_size) {
    const float* x  = (const float*)d_in[0];
    const float* wq = (const float*)d_in[1];
    const float* bq = (const float*)d_in[2];
    const float* wk = (const float*)d_in[3];
    const float* bk = (const float*)d_in[4];
    const float* wv = (const float*)d_in[5];
    const float* bv = (const float*)d_in[6];
    const float* wo = (const float*)d_in[7];
    const float* bo = (const float*)d_in[8];
    float* out = (float*)d_out;

    cudaFuncSetAttribute(qkv_attn_kernel, cudaFuncAttributeMaxDynamicSharedMemorySize, F_SMEM);
    cudaFuncSetAttribute(proj_kernel, cudaFuncAttributeMaxDynamicSharedMemorySize, SMEM_DYN);

    prep_kernel<<<8704, 256>>>(x, wq, wk, wv, wo);
    dim3 g1(8, 512);
    qkv_attn_kernel<<<g1, 128, F_SMEM>>>(bq, bk, bv);
    dim3 g3(4, 256);
    proj_kernel<<<g3, 256, SMEM_DYN>>>(x, bo, out);
}

// round 14
// speedup vs baseline: 1.5748x; 1.0282x over previous
#include <cuda_runtime.h>
#include <cuda_bf16.h>
#include <stdint.h>

#define NWIN   512
#define T_     64
#define C_     512
#define NH_    8
#define D_     64
#define MROWS  32768
#define SCALE_ 0.125f

// ---------------- scratch ----------------
// g_xw: per-window tiles [win 512][kc 16] of 64 rows x 32 bf16 (4KB, R10-swizzled)
// g_wT: per-head tiles   [head 8][kc 16] of 192 rows (q|k|v cols) x 32 bf16 (12KB, R10-swizzled)
// g_o / g_woT: R12 format — [rowblk][kc64] 16KB tiles of 128 rows x 64 bf16, SW128
__device__ __nv_bfloat16 g_xw [MROWS * C_];
__device__ __nv_bfloat16 g_o  [MROWS * C_];
__device__ __nv_bfloat16 g_wT [1536 * C_];
__device__ __nv_bfloat16 g_woT[C_ * C_];

// ---------------- asm helpers ----------------
__device__ __forceinline__ void mma16816(float* c, uint32_t a0, uint32_t a1, uint32_t a2, uint32_t a3,
                                         uint32_t b0, uint32_t b1) {
    asm volatile(
        "mma.sync.aligned.m16n8k16.row.col.f32.bf16.bf16.f32 "
        "{%0,%1,%2,%3}, {%4,%5,%6,%7}, {%8,%9}, {%0,%1,%2,%3};"
        : "+f"(c[0]), "+f"(c[1]), "+f"(c[2]), "+f"(c[3])
        : "r"(a0), "r"(a1), "r"(a2), "r"(a3), "r"(b0), "r"(b1));
}
__device__ __forceinline__ void ldsm4(uint32_t* r, uint32_t addr) {
    asm volatile("ldmatrix.sync.aligned.m8n8.x4.shared.b16 {%0,%1,%2,%3}, [%4];"
                 : "=r"(r[0]), "=r"(r[1]), "=r"(r[2]), "=r"(r[3]) : "r"(addr));
}
__device__ __forceinline__ void ldsm4t(uint32_t* r, uint32_t addr) {
    asm volatile("ldmatrix.sync.aligned.m8n8.x4.trans.shared.b16 {%0,%1,%2,%3}, [%4];"
                 : "=r"(r[0]), "=r"(r[1]), "=r"(r[2]), "=r"(r[3]) : "r"(addr));
}
__device__ __forceinline__ uint32_t smem_u32(const void* p) {
    return (uint32_t)__cvta_generic_to_shared(p);
}
__device__ __forceinline__ uint32_t pack_bf16(float a, float b) {
    __nv_bfloat162 t = __floats2bfloat162_rn(a, b);
    return *reinterpret_cast<uint32_t*>(&t);
}
__device__ __forceinline__ void cpbulk(uint32_t dst, const void* src, uint32_t bytes, uint32_t mbar) {
    asm volatile("cp.async.bulk.shared::cta.global.mbarrier::complete_tx::bytes [%0], [%1], %2, [%3];"
                 :: "r"(dst), "l"(src), "r"(bytes), "r"(mbar) : "memory");
}
#define MBARRIER_INIT(mbar, count) \
    asm volatile("mbarrier.init.shared.b64 [%0], %1;" :: "r"((uint32_t)(mbar)), "r"((uint32_t)(count)) : "memory")
#define MBARRIER_EXPECT_TX(mbar, tx) \
    asm volatile("mbarrier.arrive.expect_tx.shared.b64 _, [%0], %1;" :: "r"((uint32_t)(mbar)), "r"((uint32_t)(tx)) : "memory")
#define MBARRIER_WAIT_PARITY(mbar, parity) do { \
    uint32_t _mbar = (uint32_t)(mbar); \
    uint32_t _parity = (uint32_t)(parity); \
    uint32_t _done; \
    asm volatile( \
        "{\n\t.reg .pred p;\n\t" \
        "mbarrier.try_wait.parity.acquire.cta.shared::cta.b64 p, [%1], %2;\n\t" \
        "selp.b32 %0, 1, 0, p;\n\t}" \
        : "=r"(_done) : "r"(_mbar), "r"(_parity) : "memory"); \
    if (!_done) { \
        asm volatile( \
            "{\n\t.reg .pred P1;\n\t" \
            "WAIT_LOOP_%=:\n\t" \
            "mbarrier.try_wait.parity.acquire.cta.shared::cta.b64 P1, [%0], %1, 0x989680;\n\t" \
            "@P1 bra.uni WAIT_DONE_%=;\n\t" \
            "bra.uni WAIT_LOOP_%=;\n\t" \
            "WAIT_DONE_%=:\n\t}" \
            :: "r"(_mbar), "r"(_parity) : "memory"); \
    } \
} while(0)

// R10 swizzle: byte address of 16B chunk c (0..3) of logical 64B row `row`.
__device__ __forceinline__ uint32_t sw_addr(int row, int c) {
    return (uint32_t)(((row >> 1) << 7) + (((((row & 1) << 2) | c) ^ ((row >> 1) & 7)) << 4));
}

// ---------------- K0: prep — gather x, tile weights ----------------
__global__ __launch_bounds__(256) void prep_kernel(const float* __restrict__ x,
                                                   const float* __restrict__ wq,
                                                   const float* __restrict__ wk,
                                                   const float* __restrict__ wv,
                                                   const float* __restrict__ wo) {
    int bid = blockIdx.x;
    if (bid < 8192) {
        int idx = bid * 256 + threadIdx.x;        // 0..2097151
        int gr = idx >> 6, u = idx & 63;
        int win = gr >> 6, t = gr & 63;
        int b = win >> 6, wh = (win >> 3) & 7, ww = win & 7;
        int i = t >> 3, j = t & 7;
        int r  = (wh * 8 + i + 4) & 63;
        int cc = (ww * 8 + j + 4) & 63;
        const float* src = x + (((b * 64 + r) * 64 + cc) << 9) + u * 8;
        float4 f0 = *reinterpret_cast<const float4*>(src);
        float4 f1 = *reinterpret_cast<const float4*>(src + 4);
        uint4 o;
        o.x = pack_bf16(f0.x, f0.y); o.y = pack_bf16(f0.z, f0.w);
        o.z = pack_bf16(f1.x, f1.y); o.w = pack_bf16(f1.z, f1.w);
        int kc = u >> 2, c = u & 3, trow = gr & 63;
        size_t off = (size_t)(win * 16 + kc) * 4096 + sw_addr(trow, c);
        *reinterpret_cast<uint4*>((char*)g_xw + off) = o;
    } else if (bid < 8576) {
        int idx = (bid - 8192) * 256 + threadIdx.x;  // 0..98303
        int jcol = idx >> 6, u = idx & 63;
        int sel = jcol >> 9, jj = jcol & 511;
        int h = jj >> 6, d = jj & 63;
        const float* w = (sel == 0) ? wq : (sel == 1) ? wk : wv;
        float v[8];
        #pragma unroll
        for (int kk = 0; kk < 8; kk++) v[kk] = w[(u * 8 + kk) * 512 + jj];
        uint4 o;
        o.x = pack_bf16(v[0], v[1]); o.y = pack_bf16(v[2], v[3]);
        o.z = pack_bf16(v[4], v[5]); o.w = pack_bf16(v[6], v[7]);
        int kc = u >> 2, c = u & 3, brow = sel * 64 + d;
        size_t off = (size_t)(h * 16 + kc) * 12288 + sw_addr(brow, c);
        *reinterpret_cast<uint4*>((char*)g_wT + off) = o;
    } else {
        int idx = (bid - 8576) * 256 + threadIdx.x;  // 0..32767
        int jcol = idx >> 6, u = idx & 63;
        float v[8];
        #pragma unroll
        for (int kk = 0; kk < 8; kk++) v[kk] = wo[(u * 8 + kk) * 512 + jcol];
        uint4 o;
        o.x = pack_bf16(v[0], v[1]); o.y = pack_bf16(v[2], v[3]);
        o.z = pack_bf16(v[4], v[5]); o.w = pack_bf16(v[6], v[7]);
        int kc = u >> 3, c = u & 7, trow = jcol & 127;
        size_t e = (size_t)((jcol >> 7) * 8 + kc) * 8192 + trow * 64 + ((c ^ (trow & 7)) << 3);
        *reinterpret_cast<uint4*>(g_woT + e) = o;
    }
}

// ---------------- K1: FUSED qkv GEMM + attention per (head, window) — unchanged R13 ----------------
#define F_STAGE   16384
#define F_SMEM    (128 + 3 * F_STAGE + 3 * 8192)

__global__ __launch_bounds__(128, 3) void qkv_attn_kernel(const float* __restrict__ bq,
                                                          const float* __restrict__ bk,
                                                          const float* __restrict__ bv) {
    extern __shared__ char dyn[];
    const int head = blockIdx.x, win = blockIdx.y;
    const int tid = threadIdx.x, lane = tid & 31, warp = tid >> 5;
    const int wm = warp >> 1, wn = warp & 1;
    const int g = lane >> 2, tg = lane & 3;

    const uint32_t dsm = (smem_u32(dyn) + 127) & ~127u;
    const uint32_t stg0 = dsm + 128;
    const uint32_t qkv0 = stg0 + 3 * F_STAGE;

    if (tid == 0) {
        MBARRIER_INIT(dsm + 0, 1);
        MBARRIER_INIT(dsm + 8, 1);
        MBARRIER_INIT(dsm + 16, 1);
    }
    __syncthreads();

    const char* Abase = (const char*)g_xw + (size_t)win * 65536;
    const char* Bbase = (const char*)g_wT + (size_t)head * 196608;

    if (tid == 0) {
        MBARRIER_EXPECT_TX(dsm + 0, F_STAGE);
        cpbulk(stg0, Abase, 4096, dsm + 0);
        cpbulk(stg0 + 4096, Bbase, 12288, dsm + 0);
        MBARRIER_EXPECT_TX(dsm + 8, F_STAGE);
        cpbulk(stg0 + F_STAGE, Abase + 4096, 4096, dsm + 8);
        cpbulk(stg0 + F_STAGE + 4096, Bbase + 12288, 12288, dsm + 8);
    }

    float acc[2][12][4];
    #pragma unroll
    for (int mi = 0; mi < 2; mi++)
        #pragma unroll
        for (int nt = 0; nt < 12; nt++)
            #pragma unroll
            for (int e = 0; e < 4; e++) acc[mi][nt][e] = 0.f;

    const int r_a = wm * 32 + (lane & 15);
    const int hiA = lane >> 4;
    const uint32_t aOff0 = sw_addr(r_a, hiA), aOff1 = sw_addr(r_a, hiA + 2);
    const int r_b = wn * 96 + ((lane >> 4) & 1) * 8 + (lane & 7);
    const int hiB = (lane >> 3) & 1;
    const uint32_t bOff0 = sw_addr(r_b, hiB), bOff1 = sw_addr(r_b, hiB + 2);

    for (int kc = 0; kc < 16; kc++) {
        const int s = kc % 3;
        MBARRIER_WAIT_PARITY(dsm + s * 8, (uint32_t)((kc / 3) & 1));
        const uint32_t sA = stg0 + s * F_STAGE;
        const uint32_t sB = sA + 4096;
        #pragma unroll
        for (int ks = 0; ks < 2; ks++) {
            const uint32_t aOff = sA + (ks ? aOff1 : aOff0);
            const uint32_t bOff = sB + (ks ? bOff1 : bOff0);
            uint32_t a[2][4], bb[6][4];
            #pragma unroll
            for (int mi = 0; mi < 2; mi++)
                ldsm4(a[mi], aOff + mi * 1024);
            #pragma unroll
            for (int p = 0; p < 6; p++)
                ldsm4(bb[p], bOff + p * 1024);
            #pragma unroll
            for (int mi = 0; mi < 2; mi++)
                #pragma unroll
                for (int nt = 0; nt < 12; nt++)
                    mma16816(acc[mi][nt], a[mi][0], a[mi][1], a[mi][2], a[mi][3],
                             bb[nt >> 1][(nt & 1) * 2], bb[nt >> 1][(nt & 1) * 2 + 1]);
        }
        __syncthreads();
        if (kc < 14 && tid == 0) {
            const int kn = kc + 2, sn = kn % 3;
            MBARRIER_EXPECT_TX(dsm + sn * 8, F_STAGE);
            cpbulk(stg0 + sn * F_STAGE, Abase + kn * 4096, 4096, dsm + sn * 8);
            cpbulk(stg0 + sn * F_STAGE + 4096, Bbase + (size_t)kn * 12288, 12288, dsm + sn * 8);
        }
    }

    #pragma unroll
    for (int mi = 0; mi < 2; mi++) {
        #pragma unroll
        for (int nt = 0; nt < 12; nt++) {
            const int col = wn * 96 + nt * 8 + 2 * tg;
            const int sel = col >> 6, d = col & 63;
            const float* bias = (sel == 0) ? bq : (sel == 1) ? bk : bv;
            const float b0f = bias[head * 64 + d], b1f = bias[head * 64 + d + 1];
            const uint32_t base = qkv0 + sel * 8192;
            const int row0 = wm * 32 + mi * 16 + g, row1 = row0 + 8;
            const uint32_t a0 = base + row0 * 128 + ((((d >> 3) ^ (row0 & 7))) << 4) + (d & 7) * 2;
            const uint32_t a1 = base + row1 * 128 + ((((d >> 3) ^ (row1 & 7))) << 4) + (d & 7) * 2;
            uint32_t v0 = pack_bf16(acc[mi][nt][0] + b0f, acc[mi][nt][1] + b1f);
            uint32_t v1 = pack_bf16(acc[mi][nt][2] + b0f, acc[mi][nt][3] + b1f);
            asm volatile("st.shared.b32 [%0], %1;" :: "r"(a0), "r"(v0) : "memory");
            asm volatile("st.shared.b32 [%0], %1;" :: "r"(a1), "r"(v1) : "memory");
        }
    }
    __syncthreads();

    const uint32_t Qs = qkv0, Ks = qkv0 + 8192, Vs = qkv0 + 16384;
    const int qRow = warp * 16 + (lane & 15);
    const int hiQ = lane >> 4, swzQ = qRow & 7;
    const uint32_t qBase = Qs + qRow * 128;
    const int kRow = ((lane >> 4) & 1) * 8 + (lane & 7);
    const int hiK = (lane >> 3) & 1, swzK = kRow & 7;
    const uint32_t kBase = Ks + kRow * 128;
    const int vRow = (lane & 7) + ((lane >> 3) & 1) * 8;
    const int hiV = (lane >> 4) & 1, swzV = vRow & 7;
    const uint32_t vBase = Vs + vRow * 128;

    float sc[8][4];
    #pragma unroll
    for (int nt = 0; nt < 8; nt++) { sc[nt][0]=0.f; sc[nt][1]=0.f; sc[nt][2]=0.f; sc[nt][3]=0.f; }
    #pragma unroll
    for (int ks = 0; ks < 4; ks++) {
        uint32_t a[4], bb[4][4];
        ldsm4(a, qBase + (((ks * 2 + hiQ) ^ swzQ) << 4));
        #pragma unroll
        for (int p = 0; p < 4; p++)
            ldsm4(bb[p], kBase + p * 2048 + (((ks * 2 + hiK) ^ swzK) << 4));
        #pragma unroll
        for (int nt = 0; nt < 8; nt++)
            mma16816(sc[nt], a[0], a[1], a[2], a[3],
                     bb[nt >> 1][(nt & 1) * 2], bb[nt >> 1][(nt & 1) * 2 + 1]);
    }

    float mx0 = -1e30f, mx1 = -1e30f;
    #pragma unroll
    for (int nt = 0; nt < 8; nt++) {
        mx0 = fmaxf(mx0, fmaxf(sc[nt][0], sc[nt][1]));
        mx1 = fmaxf(mx1, fmaxf(sc[nt][2], sc[nt][3]));
    }
    mx0 = fmaxf(mx0, __shfl_xor_sync(0xffffffff, mx0, 1));
    mx0 = fmaxf(mx0, __shfl_xor_sync(0xffffffff, mx0, 2));
    mx1 = fmaxf(mx1, __shfl_xor_sync(0xffffffff, mx1, 1));
    mx1 = fmaxf(mx1, __shfl_xor_sync(0xffffffff, mx1, 2));
    float s0 = 0.f, s1 = 0.f;
    #pragma unroll
    for (int nt = 0; nt < 8; nt++) {
        sc[nt][0] = __expf((sc[nt][0] - mx0) * SCALE_);
        sc[nt][1] = __expf((sc[nt][1] - mx0) * SCALE_);
        sc[nt][2] = __expf((sc[nt][2] - mx1) * SCALE_);
        sc[nt][3] = __expf((sc[nt][3] - mx1) * SCALE_);
        s0 += sc[nt][0] + sc[nt][1];
        s1 += sc[nt][2] + sc[nt][3];
    }
    s0 += __shfl_xor_sync(0xffffffff, s0, 1);
    s0 += __shfl_xor_sync(0xffffffff, s0, 2);
    s1 += __shfl_xor_sync(0xffffffff, s1, 1);
    s1 += __shfl_xor_sync(0xffffffff, s1, 2);
    const float i0 = 1.f / s0, i1 = 1.f / s1;

    uint32_t pa[8][2];
    #pragma unroll
    for (int nt = 0; nt < 8; nt++) {
        pa[nt][0] = pack_bf16(sc[nt][0] * i0, sc[nt][1] * i0);
        pa[nt][1] = pack_bf16(sc[nt][2] * i1, sc[nt][3] * i1);
    }

    float oc[8][4];
    #pragma unroll
    for (int nt = 0; nt < 8; nt++) { oc[nt][0]=0.f; oc[nt][1]=0.f; oc[nt][2]=0.f; oc[nt][3]=0.f; }
    #pragma unroll
    for (int ks = 0; ks < 4; ks++) {
        uint32_t bb[4][4];
        #pragma unroll
        for (int p = 0; p < 4; p++)
            ldsm4t(bb[p], vBase + ks * 2048 + (((p * 2 + hiV) ^ swzV) << 4));
        uint32_t a0 = pa[2 * ks][0], a1 = pa[2 * ks][1];
        uint32_t a2 = pa[2 * ks + 1][0], a3 = pa[2 * ks + 1][1];
        #pragma unroll
        for (int nt = 0; nt < 8; nt++)
            mma16816(oc[nt], a0, a1, a2, a3,
                     bb[nt >> 1][(nt & 1) * 2], bb[nt >> 1][(nt & 1) * 2 + 1]);
    }

    const int r0 = warp * 16 + g;
    const size_t tbase = (size_t)((win >> 1) * 8 + head) * 8192;
    const int trow0 = (win & 1) * 64 + r0;
    #pragma unroll
    for (int nt = 0; nt < 8; nt++) {
        const int trow1 = trow0 + 8;
        size_t e0 = tbase + trow0 * 64 + ((nt ^ (trow0 & 7)) << 3) + 2 * tg;
        size_t e1 = tbase + trow1 * 64 + ((nt ^ (trow1 & 7)) << 3) + 2 * tg;
        *reinterpret_cast<uint32_t*>(g_o + e0) = pack_bf16(oc[nt][0], oc[nt][1]);
        *reinterpret_cast<uint32_t*>(g_o + e1) = pack_bf16(oc[nt][2], oc[nt][3]);
    }
}

// ---------------- K3: proj — BM=64, BN=128, BK=64, 128 threads, 3 bulk stages ----------------
#define P_STAGE   24576                        // A 8KB + B 16KB
#define P_SMEM    (128 + 3 * P_STAGE)

__global__ __launch_bounds__(128, 3) void proj_kernel(const float* __restrict__ x,
                                                      const float* __restrict__ bo,
                                                      float* __restrict__ out) {
    extern __shared__ char dyn[];
    const int tid = threadIdx.x, lane = tid & 31, warp = tid >> 5;
    const int g = lane >> 2, tg = lane & 3;
    const int wm = warp >> 1, wn = warp & 1;       // 2 x 2
    const int mbase = blockIdx.y * 64, nbase = blockIdx.x * 128;

    const uint32_t dsm = (smem_u32(dyn) + 127) & ~127u;
    const uint32_t stg0 = dsm + 128;

    if (tid == 0) {
        MBARRIER_INIT(dsm + 0, 1);
        MBARRIER_INIT(dsm + 8, 1);
        MBARRIER_INIT(dsm + 16, 1);
    }
    __syncthreads();

    // A: 64-row half of a 128-row g_o tile (rows contiguous per chunk)
    const char* Abase = (const char*)g_o + (size_t)(blockIdx.y >> 1) * 131072
                      + (size_t)(blockIdx.y & 1) * 8192;
    const char* Bbase = (const char*)g_woT + (size_t)blockIdx.x * 131072;

    if (tid == 0) {
        MBARRIER_EXPECT_TX(dsm + 0, P_STAGE);
        cpbulk(stg0, Abase, 8192, dsm + 0);
        cpbulk(stg0 + 8192, Bbase, 16384, dsm + 0);
        MBARRIER_EXPECT_TX(dsm + 8, P_STAGE);
        cpbulk(stg0 + P_STAGE, Abase + 16384, 8192, dsm + 8);
        cpbulk(stg0 + P_STAGE + 8192, Bbase + 16384, 16384, dsm + 8);
    }

    float acc[2][8][4];
    #pragma unroll
    for (int mi = 0; mi < 2; mi++)
        #pragma unroll
        for (int nt = 0; nt < 8; nt++)
            #pragma unroll
            for (int e = 0; e < 4; e++) acc[mi][nt][e] = 0.f;

    const int rowA = wm * 32 + (lane & 15);
    const uint32_t aRow = (uint32_t)rowA * 128;
    const int hiA = lane >> 4, swzA = rowA & 7;
    const int rowB = wn * 64 + ((lane >> 4) & 1) * 8 + (lane & 7);
    const uint32_t bRow = (uint32_t)rowB * 128;
    const int hiB = (lane >> 3) & 1, swzB = rowB & 7;

    for (int kc = 0; kc < 8; kc++) {
        const int s = kc % 3;
        MBARRIER_WAIT_PARITY(dsm + s * 8, (uint32_t)((kc / 3) & 1));

        const uint32_t sA = stg0 + s * P_STAGE;
        const uint32_t sB = sA + 8192;
        #pragma unroll
        for (int ks = 0; ks < 4; ks++) {
            const uint32_t colA = (uint32_t)(((2 * ks + hiA) ^ swzA) << 4);
            const uint32_t colB = (uint32_t)(((2 * ks + hiB) ^ swzB) << 4);
            uint32_t a[2][4], bb[4][4];
            #pragma unroll
            for (int mi = 0; mi < 2; mi++)
                ldsm4(a[mi], sA + aRow + mi * 2048 + colA);
            #pragma unroll
            for (int p = 0; p < 4; p++)
                ldsm4(bb[p], sB + bRow + p * 2048 + colB);
            #pragma unroll
            for (int mi = 0; mi < 2; mi++)
                #pragma unroll
                for (int nt = 0; nt < 8; nt++)
                    mma16816(acc[mi][nt], a[mi][0], a[mi][1], a[mi][2], a[mi][3],
                             bb[nt >> 1][(nt & 1) * 2], bb[nt >> 1][(nt & 1) * 2 + 1]);
        }
        __syncthreads();
        if (kc < 6 && tid == 0) {
            const int kn = kc + 2, sn = kn % 3;
            MBARRIER_EXPECT_TX(dsm + sn * 8, P_STAGE);
            cpbulk(stg0 + sn * P_STAGE, Abase + kn * 16384, 8192, dsm + sn * 8);
            cpbulk(stg0 + sn * P_STAGE + 8192, Bbase + kn * 16384, 16384, dsm + sn * 8);
        }
    }

    // epilogue: scatter (inverse roll) + bias + residual
    #pragma unroll
    for (int mi = 0; mi < 2; mi++) {
        #pragma unroll
        for (int half = 0; half < 2; half++) {
            int row = mbase + wm * 32 + mi * 16 + g + half * 8;
            int win = row >> 6, t = row & 63;
            int b = win >> 6, wh = (win >> 3) & 7, ww = win & 7;
            int i = t >> 3, j = t & 7;
            int r  = (wh * 8 + i + 4) & 63;
            int cc = (ww * 8 + j + 4) & 63;
            size_t off = (size_t)((b * 64 + r) * 64 + cc) * C_;
            #pragma unroll
            for (int nt = 0; nt < 8; nt++) {
                int col = nbase + wn * 64 + nt * 8 + 2 * tg;
                float2 xr = *reinterpret_cast<const float2*>(x + off + col);
                float2 o;
                o.x = acc[mi][nt][2 * half + 0] + bo[col]     + xr.x;
                o.y = acc[mi][nt][2 * half + 1] + bo[col + 1] + xr.y;
                *reinterpret_cast<float2*>(out + off + col) = o;
            }
        }
    }
}

// ---------------- launch ----------------
extern "C" void kernel_launch(void* const* d_in, const int* in_sizes, int n_in,
                              void* d_out, int out_size) {
    const float* x  = (const float*)d_in[0];
    const float* wq = (const float*)d_in[1];
    const float* bq = (const float*)d_in[2];
    const float* wk = (const float*)d_in[3];
    const float* bk = (const float*)d_in[4];
    const float* wv = (const float*)d_in[5];
    const float* bv = (const float*)d_in[6];
    const float* wo = (const float*)d_in[7];
    const float* bo = (const float*)d_in[8];
    float* out = (float*)d_out;

    cudaFuncSetAttribute(qkv_attn_kernel, cudaFuncAttributeMaxDynamicSharedMemorySize, F_SMEM);
    cudaFuncSetAttribute(proj_kernel, cudaFuncAttributeMaxDynamicSharedMemorySize, P_SMEM);

    prep_kernel<<<8704, 256>>>(x, wq, wk, wv, wo);
    dim3 g1(8, 512);
    qkv_attn_kernel<<<g1, 128, F_SMEM>>>(bq, bk, bv);
    dim3 g3(4, 512);
    proj_kernel<<<g3, 128, P_SMEM>>>(x, bo, out);
}

// round 15
// speedup vs baseline: 1.5770x; 1.0014x over previous
#include <cuda_runtime.h>
#include <cuda_bf16.h>
#include <stdint.h>

#define NWIN   512
#define T_     64
#define C_     512
#define NH_    8
#define D_     64
#define MROWS  32768
#define SCALE_ 0.125f

// ---------------- scratch ----------------
// g_xw: per-window tiles [win 512][kc 16] of 64 rows x 32 bf16 (4KB, R10-swizzled)
// g_wT: per-head tiles   [head 8][kc 16] of 192 rows (q|k|v cols) x 32 bf16 (12KB, R10-swizzled)
// g_o / g_woT: R12 format — [rowblk][kc64] 16KB tiles of 128 rows x 64 bf16, SW128
__device__ __nv_bfloat16 g_xw [MROWS * C_];
__device__ __nv_bfloat16 g_o  [MROWS * C_];
__device__ __nv_bfloat16 g_wT [1536 * C_];
__device__ __nv_bfloat16 g_woT[C_ * C_];

// ---------------- asm helpers ----------------
__device__ __forceinline__ void mma16816(float* c, uint32_t a0, uint32_t a1, uint32_t a2, uint32_t a3,
                                         uint32_t b0, uint32_t b1) {
    asm volatile(
        "mma.sync.aligned.m16n8k16.row.col.f32.bf16.bf16.f32 "
        "{%0,%1,%2,%3}, {%4,%5,%6,%7}, {%8,%9}, {%0,%1,%2,%3};"
        : "+f"(c[0]), "+f"(c[1]), "+f"(c[2]), "+f"(c[3])
        : "r"(a0), "r"(a1), "r"(a2), "r"(a3), "r"(b0), "r"(b1));
}
__device__ __forceinline__ void ldsm4(uint32_t* r, uint32_t addr) {
    asm volatile("ldmatrix.sync.aligned.m8n8.x4.shared.b16 {%0,%1,%2,%3}, [%4];"
                 : "=r"(r[0]), "=r"(r[1]), "=r"(r[2]), "=r"(r[3]) : "r"(addr));
}
__device__ __forceinline__ void ldsm4t(uint32_t* r, uint32_t addr) {
    asm volatile("ldmatrix.sync.aligned.m8n8.x4.trans.shared.b16 {%0,%1,%2,%3}, [%4];"
                 : "=r"(r[0]), "=r"(r[1]), "=r"(r[2]), "=r"(r[3]) : "r"(addr));
}
__device__ __forceinline__ uint32_t smem_u32(const void* p) {
    return (uint32_t)__cvta_generic_to_shared(p);
}
__device__ __forceinline__ uint32_t pack_bf16(float a, float b) {
    __nv_bfloat162 t = __floats2bfloat162_rn(a, b);
    return *reinterpret_cast<uint32_t*>(&t);
}
__device__ __forceinline__ void cpbulk(uint32_t dst, const void* src, uint32_t bytes, uint32_t mbar) {
    asm volatile("cp.async.bulk.shared::cta.global.mbarrier::complete_tx::bytes [%0], [%1], %2, [%3];"
                 :: "r"(dst), "l"(src), "r"(bytes), "r"(mbar) : "memory");
}
#define MBARRIER_INIT(mbar, count) \
    asm volatile("mbarrier.init.shared.b64 [%0], %1;" :: "r"((uint32_t)(mbar)), "r"((uint32_t)(count)) : "memory")
#define MBARRIER_EXPECT_TX(mbar, tx) \
    asm volatile("mbarrier.arrive.expect_tx.shared.b64 _, [%0], %1;" :: "r"((uint32_t)(mbar)), "r"((uint32_t)(tx)) : "memory")
#define MBARRIER_WAIT_PARITY(mbar, parity) do { \
    uint32_t _mbar = (uint32_t)(mbar); \
    uint32_t _parity = (uint32_t)(parity); \
    uint32_t _done; \
    asm volatile( \
        "{\n\t.reg .pred p;\n\t" \
        "mbarrier.try_wait.parity.acquire.cta.shared::cta.b64 p, [%1], %2;\n\t" \
        "selp.b32 %0, 1, 0, p;\n\t}" \
        : "=r"(_done) : "r"(_mbar), "r"(_parity) : "memory"); \
    if (!_done) { \
        asm volatile( \
            "{\n\t.reg .pred P1;\n\t" \
            "WAIT_LOOP_%=:\n\t" \
            "mbarrier.try_wait.parity.acquire.cta.shared::cta.b64 P1, [%0], %1, 0x989680;\n\t" \
            "@P1 bra.uni WAIT_DONE_%=;\n\t" \
            "bra.uni WAIT_LOOP_%=;\n\t" \
            "WAIT_DONE_%=:\n\t}" \
            :: "r"(_mbar), "r"(_parity) : "memory"); \
    } \
} while(0)

// R10 swizzle: byte address of 16B chunk c (0..3) of logical 64B row `row`.
__device__ __forceinline__ uint32_t sw_addr(int row, int c) {
    return (uint32_t)(((row >> 1) << 7) + (((((row & 1) << 2) | c) ^ ((row >> 1) & 7)) << 4));
}

// ---------------- K0: prep — gather x, tile weights ----------------
__global__ __launch_bounds__(256) void prep_kernel(const float* __restrict__ x,
                                                   const float* __restrict__ wq,
                                                   const float* __restrict__ wk,
                                                   const float* __restrict__ wv,
                                                   const float* __restrict__ wo) {
    int bid = blockIdx.x;
    if (bid < 8192) {
        int idx = bid * 256 + threadIdx.x;        // 0..2097151
        int gr = idx >> 6, u = idx & 63;
        int win = gr >> 6, t = gr & 63;
        int b = win >> 6, wh = (win >> 3) & 7, ww = win & 7;
        int i = t >> 3, j = t & 7;
        int r  = (wh * 8 + i + 4) & 63;
        int cc = (ww * 8 + j + 4) & 63;
        const float* src = x + (((b * 64 + r) * 64 + cc) << 9) + u * 8;
        float4 f0 = *reinterpret_cast<const float4*>(src);
        float4 f1 = *reinterpret_cast<const float4*>(src + 4);
        uint4 o;
        o.x = pack_bf16(f0.x, f0.y); o.y = pack_bf16(f0.z, f0.w);
        o.z = pack_bf16(f1.x, f1.y); o.w = pack_bf16(f1.z, f1.w);
        int kc = u >> 2, c = u & 3, trow = gr & 63;
        size_t off = (size_t)(win * 16 + kc) * 4096 + sw_addr(trow, c);
        *reinterpret_cast<uint4*>((char*)g_xw + off) = o;
    } else if (bid < 8576) {
        int idx = (bid - 8192) * 256 + threadIdx.x;  // 0..98303
        int jcol = idx >> 6, u = idx & 63;
        int sel = jcol >> 9, jj = jcol & 511;
        int h = jj >> 6, d = jj & 63;
        const float* w = (sel == 0) ? wq : (sel == 1) ? wk : wv;
        float v[8];
        #pragma unroll
        for (int kk = 0; kk < 8; kk++) v[kk] = w[(u * 8 + kk) * 512 + jj];
        uint4 o;
        o.x = pack_bf16(v[0], v[1]); o.y = pack_bf16(v[2], v[3]);
        o.z = pack_bf16(v[4], v[5]); o.w = pack_bf16(v[6], v[7]);
        int kc = u >> 2, c = u & 3, brow = sel * 64 + d;
        size_t off = (size_t)(h * 16 + kc) * 12288 + sw_addr(brow, c);
        *reinterpret_cast<uint4*>((char*)g_wT + off) = o;
    } else {
        int idx = (bid - 8576) * 256 + threadIdx.x;  // 0..32767
        int jcol = idx >> 6, u = idx & 63;
        float v[8];
        #pragma unroll
        for (int kk = 0; kk < 8; kk++) v[kk] = wo[(u * 8 + kk) * 512 + jcol];
        uint4 o;
        o.x = pack_bf16(v[0], v[1]); o.y = pack_bf16(v[2], v[3]);
        o.z = pack_bf16(v[4], v[5]); o.w = pack_bf16(v[6], v[7]);
        int kc = u >> 3, c = u & 7, trow = jcol & 127;
        size_t e = (size_t)((jcol >> 7) * 8 + kc) * 8192 + trow * 64 + ((c ^ (trow & 7)) << 3);
        *reinterpret_cast<uint4*>(g_woT + e) = o;
    }
}

// ---------------- K1: FUSED qkv GEMM + attention per (head, window) ----------------
#define F_STAGE   16384
#define F_SMEM    (128 + 3 * F_STAGE + 3 * 8192)

__global__ __launch_bounds__(128, 3) void qkv_attn_kernel(const float* __restrict__ bq,
                                                          const float* __restrict__ bk,
                                                          const float* __restrict__ bv) {
    extern __shared__ char dyn[];
    const int head = blockIdx.x, win = blockIdx.y;
    const int tid = threadIdx.x, lane = tid & 31, warp = tid >> 5;
    const int wm = warp >> 1, wn = warp & 1;
    const int g = lane >> 2, tg = lane & 3;

    const uint32_t dsm = (smem_u32(dyn) + 127) & ~127u;
    const uint32_t stg0 = dsm + 128;
    const uint32_t qkv0 = stg0 + 3 * F_STAGE;

    if (tid == 0) {
        MBARRIER_INIT(dsm + 0, 1);
        MBARRIER_INIT(dsm + 8, 1);
        MBARRIER_INIT(dsm + 16, 1);
    }
    __syncthreads();

    const char* Abase = (const char*)g_xw + (size_t)win * 65536;
    const char* Bbase = (const char*)g_wT + (size_t)head * 196608;

    if (tid == 0) {
        MBARRIER_EXPECT_TX(dsm + 0, F_STAGE);
        cpbulk(stg0, Abase, 4096, dsm + 0);
        cpbulk(stg0 + 4096, Bbase, 12288, dsm + 0);
        MBARRIER_EXPECT_TX(dsm + 8, F_STAGE);
        cpbulk(stg0 + F_STAGE, Abase + 4096, 4096, dsm + 8);
        cpbulk(stg0 + F_STAGE + 4096, Bbase + 12288, 12288, dsm + 8);
    }

    float acc[2][12][4];
    #pragma unroll
    for (int mi = 0; mi < 2; mi++)
        #pragma unroll
        for (int nt = 0; nt < 12; nt++)
            #pragma unroll
            for (int e = 0; e < 4; e++) acc[mi][nt][e] = 0.f;

    const int r_a = wm * 32 + (lane & 15);
    const int hiA = lane >> 4;
    const uint32_t aOff0 = sw_addr(r_a, hiA), aOff1 = sw_addr(r_a, hiA + 2);
    const int r_b = wn * 96 + ((lane >> 4) & 1) * 8 + (lane & 7);
    const int hiB = (lane >> 3) & 1;
    const uint32_t bOff0 = sw_addr(r_b, hiB), bOff1 = sw_addr(r_b, hiB + 2);

    for (int kc = 0; kc < 16; kc++) {
        const int s = kc % 3;
        MBARRIER_WAIT_PARITY(dsm + s * 8, (uint32_t)((kc / 3) & 1));
        // EARLY REFILL: slot (kc+2)%3 == (kc-1)%3 was proven free by the
        // __syncthreads at the end of iteration kc-1.
        if (kc < 14 && tid == 0) {
            const int kn = kc + 2, sn = kn % 3;
            MBARRIER_EXPECT_TX(dsm + sn * 8, F_STAGE);
            cpbulk(stg0 + sn * F_STAGE, Abase + kn * 4096, 4096, dsm + sn * 8);
            cpbulk(stg0 + sn * F_STAGE + 4096, Bbase + (size_t)kn * 12288, 12288, dsm + sn * 8);
        }
        const uint32_t sA = stg0 + s * F_STAGE;
        const uint32_t sB = sA + 4096;
        #pragma unroll
        for (int ks = 0; ks < 2; ks++) {
            const uint32_t aOff = sA + (ks ? aOff1 : aOff0);
            const uint32_t bOff = sB + (ks ? bOff1 : bOff0);
            uint32_t a[2][4], bb[6][4];
            #pragma unroll
            for (int mi = 0; mi < 2; mi++)
                ldsm4(a[mi], aOff + mi * 1024);
            #pragma unroll
            for (int p = 0; p < 6; p++)
                ldsm4(bb[p], bOff + p * 1024);
            #pragma unroll
            for (int mi = 0; mi < 2; mi++)
                #pragma unroll
                for (int nt = 0; nt < 12; nt++)
                    mma16816(acc[mi][nt], a[mi][0], a[mi][1], a[mi][2], a[mi][3],
                             bb[nt >> 1][(nt & 1) * 2], bb[nt >> 1][(nt & 1) * 2 + 1]);
        }
        __syncthreads();
    }

    #pragma unroll
    for (int mi = 0; mi < 2; mi++) {
        #pragma unroll
        for (int nt = 0; nt < 12; nt++) {
            const int col = wn * 96 + nt * 8 + 2 * tg;
            const int sel = col >> 6, d = col & 63;
            const float* bias = (sel == 0) ? bq : (sel == 1) ? bk : bv;
            const float b0f = bias[head * 64 + d], b1f = bias[head * 64 + d + 1];
            const uint32_t base = qkv0 + sel * 8192;
            const int row0 = wm * 32 + mi * 16 + g, row1 = row0 + 8;
            const uint32_t a0 = base + row0 * 128 + ((((d >> 3) ^ (row0 & 7))) << 4) + (d & 7) * 2;
            const uint32_t a1 = base + row1 * 128 + ((((d >> 3) ^ (row1 & 7))) << 4) + (d & 7) * 2;
            uint32_t v0 = pack_bf16(acc[mi][nt][0] + b0f, acc[mi][nt][1] + b1f);
            uint32_t v1 = pack_bf16(acc[mi][nt][2] + b0f, acc[mi][nt][3] + b1f);
            asm volatile("st.shared.b32 [%0], %1;" :: "r"(a0), "r"(v0) : "memory");
            asm volatile("st.shared.b32 [%0], %1;" :: "r"(a1), "r"(v1) : "memory");
        }
    }
    __syncthreads();

    const uint32_t Qs = qkv0, Ks = qkv0 + 8192, Vs = qkv0 + 16384;
    const int qRow = warp * 16 + (lane & 15);
    const int hiQ = lane >> 4, swzQ = qRow & 7;
    const uint32_t qBase = Qs + qRow * 128;
    const int kRow = ((lane >> 4) & 1) * 8 + (lane & 7);
    const int hiK = (lane >> 3) & 1, swzK = kRow & 7;
    const uint32_t kBase = Ks + kRow * 128;
    const int vRow = (lane & 7) + ((lane >> 3) & 1) * 8;
    const int hiV = (lane >> 4) & 1, swzV = vRow & 7;
    const uint32_t vBase = Vs + vRow * 128;

    float sc[8][4];
    #pragma unroll
    for (int nt = 0; nt < 8; nt++) { sc[nt][0]=0.f; sc[nt][1]=0.f; sc[nt][2]=0.f; sc[nt][3]=0.f; }
    #pragma unroll
    for (int ks = 0; ks < 4; ks++) {
        uint32_t a[4], bb[4][4];
        ldsm4(a, qBase + (((ks * 2 + hiQ) ^ swzQ) << 4));
        #pragma unroll
        for (int p = 0; p < 4; p++)
            ldsm4(bb[p], kBase + p * 2048 + (((ks * 2 + hiK) ^ swzK) << 4));
        #pragma unroll
        for (int nt = 0; nt < 8; nt++)
            mma16816(sc[nt], a[0], a[1], a[2], a[3],
                     bb[nt >> 1][(nt & 1) * 2], bb[nt >> 1][(nt & 1) * 2 + 1]);
    }

    float mx0 = -1e30f, mx1 = -1e30f;
    #pragma unroll
    for (int nt = 0; nt < 8; nt++) {
        mx0 = fmaxf(mx0, fmaxf(sc[nt][0], sc[nt][1]));
        mx1 = fmaxf(mx1, fmaxf(sc[nt][2], sc[nt][3]));
    }
    mx0 = fmaxf(mx0, __shfl_xor_sync(0xffffffff, mx0, 1));
    mx0 = fmaxf(mx0, __shfl_xor_sync(0xffffffff, mx0, 2));
    mx1 = fmaxf(mx1, __shfl_xor_sync(0xffffffff, mx1, 1));
    mx1 = fmaxf(mx1, __shfl_xor_sync(0xffffffff, mx1, 2));
    float s0 = 0.f, s1 = 0.f;
    #pragma unroll
    for (int nt = 0; nt < 8; nt++) {
        sc[nt][0] = __expf((sc[nt][0] - mx0) * SCALE_);
        sc[nt][1] = __expf((sc[nt][1] - mx0) * SCALE_);
        sc[nt][2] = __expf((sc[nt][2] - mx1) * SCALE_);
        sc[nt][3] = __expf((sc[nt][3] - mx1) * SCALE_);
        s0 += sc[nt][0] + sc[nt][1];
        s1 += sc[nt][2] + sc[nt][3];
    }
    s0 += __shfl_xor_sync(0xffffffff, s0, 1);
    s0 += __shfl_xor_sync(0xffffffff, s0, 2);
    s1 += __shfl_xor_sync(0xffffffff, s1, 1);
    s1 += __shfl_xor_sync(0xffffffff, s1, 2);
    const float i0 = 1.f / s0, i1 = 1.f / s1;

    uint32_t pa[8][2];
    #pragma unroll
    for (int nt = 0; nt < 8; nt++) {
        pa[nt][0] = pack_bf16(sc[nt][0] * i0, sc[nt][1] * i0);
        pa[nt][1] = pack_bf16(sc[nt][2] * i1, sc[nt][3] * i1);
    }

    float oc[8][4];
    #pragma unroll
    for (int nt = 0; nt < 8; nt++) { oc[nt][0]=0.f; oc[nt][1]=0.f; oc[nt][2]=0.f; oc[nt][3]=0.f; }
    #pragma unroll
    for (int ks = 0; ks < 4; ks++) {
        uint32_t bb[4][4];
        #pragma unroll
        for (int p = 0; p < 4; p++)
            ldsm4t(bb[p], vBase + ks * 2048 + (((p * 2 + hiV) ^ swzV) << 4));
        uint32_t a0 = pa[2 * ks][0], a1 = pa[2 * ks][1];
        uint32_t a2 = pa[2 * ks + 1][0], a3 = pa[2 * ks + 1][1];
        #pragma unroll
        for (int nt = 0; nt < 8; nt++)
            mma16816(oc[nt], a0, a1, a2, a3,
                     bb[nt >> 1][(nt & 1) * 2], bb[nt >> 1][(nt & 1) * 2 + 1]);
    }

    const int r0 = warp * 16 + g;
    const size_t tbase = (size_t)((win >> 1) * 8 + head) * 8192;
    const int trow0 = (win & 1) * 64 + r0;
    #pragma unroll
    for (int nt = 0; nt < 8; nt++) {
        const int trow1 = trow0 + 8;
        size_t e0 = tbase + trow0 * 64 + ((nt ^ (trow0 & 7)) << 3) + 2 * tg;
        size_t e1 = tbase + trow1 * 64 + ((nt ^ (trow1 & 7)) << 3) + 2 * tg;
        *reinterpret_cast<uint32_t*>(g_o + e0) = pack_bf16(oc[nt][0], oc[nt][1]);
        *reinterpret_cast<uint32_t*>(g_o + e1) = pack_bf16(oc[nt][2], oc[nt][3]);
    }
}

// ---------------- K3: proj — BM=64, BN=128, BK=64, 128 threads, 3 bulk stages ----------------
#define P_STAGE   24576
#define P_SMEM    (128 + 3 * P_STAGE)

__global__ __launch_bounds__(128, 3) void proj_kernel(const float* __restrict__ x,
                                                      const float* __restrict__ bo,
                                                      float* __restrict__ out) {
    extern __shared__ char dyn[];
    const int tid = threadIdx.x, lane = tid & 31, warp = tid >> 5;
    const int g = lane >> 2, tg = lane & 3;
    const int wm = warp >> 1, wn = warp & 1;
    const int mbase = blockIdx.y * 64, nbase = blockIdx.x * 128;

    const uint32_t dsm = (smem_u32(dyn) + 127) & ~127u;
    const uint32_t stg0 = dsm + 128;

    if (tid == 0) {
        MBARRIER_INIT(dsm + 0, 1);
        MBARRIER_INIT(dsm + 8, 1);
        MBARRIER_INIT(dsm + 16, 1);
    }
    __syncthreads();

    const char* Abase = (const char*)g_o + (size_t)(blockIdx.y >> 1) * 131072
                      + (size_t)(blockIdx.y & 1) * 8192;
    const char* Bbase = (const char*)g_woT + (size_t)blockIdx.x * 131072;

    if (tid == 0) {
        MBARRIER_EXPECT_TX(dsm + 0, P_STAGE);
        cpbulk(stg0, Abase, 8192, dsm + 0);
        cpbulk(stg0 + 8192, Bbase, 16384, dsm + 0);
        MBARRIER_EXPECT_TX(dsm + 8, P_STAGE);
        cpbulk(stg0 + P_STAGE, Abase + 16384, 8192, dsm + 8);
        cpbulk(stg0 + P_STAGE + 8192, Bbase + 16384, 16384, dsm + 8);
    }

    float acc[2][8][4];
    #pragma unroll
    for (int mi = 0; mi < 2; mi++)
        #pragma unroll
        for (int nt = 0; nt < 8; nt++)
            #pragma unroll
            for (int e = 0; e < 4; e++) acc[mi][nt][e] = 0.f;

    const int rowA = wm * 32 + (lane & 15);
    const uint32_t aRow = (uint32_t)rowA * 128;
    const int hiA = lane >> 4, swzA = rowA & 7;
    const int rowB = wn * 64 + ((lane >> 4) & 1) * 8 + (lane & 7);
    const uint32_t bRow = (uint32_t)rowB * 128;
    const int hiB = (lane >> 3) & 1, swzB = rowB & 7;

    for (int kc = 0; kc < 8; kc++) {
        const int s = kc % 3;
        MBARRIER_WAIT_PARITY(dsm + s * 8, (uint32_t)((kc / 3) & 1));
        // EARLY REFILL (same proof as fused kernel)
        if (kc < 6 && tid == 0) {
            const int kn = kc + 2, sn = kn % 3;
            MBARRIER_EXPECT_TX(dsm + sn * 8, P_STAGE);
            cpbulk(stg0 + sn * P_STAGE, Abase + kn * 16384, 8192, dsm + sn * 8);
            cpbulk(stg0 + sn * P_STAGE + 8192, Bbase + kn * 16384, 16384, dsm + sn * 8);
        }

        const uint32_t sA = stg0 + s * P_STAGE;
        const uint32_t sB = sA + 8192;
        #pragma unroll
        for (int ks = 0; ks < 4; ks++) {
            const uint32_t colA = (uint32_t)(((2 * ks + hiA) ^ swzA) << 4);
            const uint32_t colB = (uint32_t)(((2 * ks + hiB) ^ swzB) << 4);
            uint32_t a[2][4], bb[4][4];
            #pragma unroll
            for (int mi = 0; mi < 2; mi++)
                ldsm4(a[mi], sA + aRow + mi * 2048 + colA);
            #pragma unroll
            for (int p = 0; p < 4; p++)
                ldsm4(bb[p], sB + bRow + p * 2048 + colB);
            #pragma unroll
            for (int mi = 0; mi < 2; mi++)
                #pragma unroll
                for (int nt = 0; nt < 8; nt++)
                    mma16816(acc[mi][nt], a[mi][0], a[mi][1], a[mi][2], a[mi][3],
                             bb[nt >> 1][(nt & 1) * 2], bb[nt >> 1][(nt & 1) * 2 + 1]);
        }
        __syncthreads();
    }

    #pragma unroll
    for (int mi = 0; mi < 2; mi++) {
        #pragma unroll
        for (int half = 0; half < 2; half++) {
            int row = mbase + wm * 32 + mi * 16 + g + half * 8;
            int win = row >> 6, t = row & 63;
            int b = win >> 6, wh = (win >> 3) & 7, ww = win & 7;
            int i = t >> 3, j = t & 7;
            int r  = (wh * 8 + i + 4) & 63;
            int cc = (ww * 8 + j + 4) & 63;
            size_t off = (size_t)((b * 64 + r) * 64 + cc) * C_;
            #pragma unroll
            for (int nt = 0; nt < 8; nt++) {
                int col = nbase + wn * 64 + nt * 8 + 2 * tg;
                float2 xr = *reinterpret_cast<const float2*>(x + off + col);
                float2 o;
                o.x = acc[mi][nt][2 * half + 0] + bo[col]     + xr.x;
                o.y = acc[mi][nt][2 * half + 1] + bo[col + 1] + xr.y;
                *reinterpret_cast<float2*>(out + off + col) = o;
            }
        }
    }
}

// ---------------- launch ----------------
extern "C" void kernel_launch(void* const* d_in, const int* in_sizes, int n_in,
                              void* d_out, int out_size) {
    const float* x  = (const float*)d_in[0];
    const float* wq = (const float*)d_in[1];
    const float* bq = (const float*)d_in[2];
    const float* wk = (const float*)d_in[3];
    const float* bk = (const float*)d_in[4];
    const float* wv = (const float*)d_in[5];
    const float* bv = (const float*)d_in[6];
    const float* wo = (const float*)d_in[7];
    const float* bo = (const float*)d_in[8];
    float* out = (float*)d_out;

    cudaFuncSetAttribute(qkv_attn_kernel, cudaFuncAttributeMaxDynamicSharedMemorySize, F_SMEM);
    cudaFuncSetAttribute(proj_kernel, cudaFuncAttributeMaxDynamicSharedMemorySize, P_SMEM);

    prep_kernel<<<8704, 256>>>(x, wq, wk, wv, wo);
    dim3 g1(8, 512);
    qkv_attn_kernel<<<g1, 128, F_SMEM>>>(bq, bk, bv);
    dim3 g3(4, 512);
    proj_kernel<<<g3, 128, P_SMEM>>>(x, bo, out);
}

// round 16
// speedup vs baseline: 1.6103x; 1.0211x over previous
#include <cuda_runtime.h>
#include <cuda_bf16.h>
#include <stdint.h>

#define NWIN   512
#define T_     64
#define C_     512
#define NH_    8
#define D_     64
#define MROWS  32768
#define SCALE_ 0.125f

// ---------------- scratch ----------------
// g_xw: per-window tiles [win 512][kc 16] of 64 rows x 32 bf16 (4KB, R10-swizzled)
// g_wT: per-head tiles   [head 8][kc 16] of 192 rows (q|k|v cols) x 32 bf16 (12KB, R10-swizzled)
// g_o / g_woT: R12 format — [rowblk][kc64] 16KB tiles of 128 rows x 64 bf16, SW128
__device__ __nv_bfloat16 g_xw [MROWS * C_];
__device__ __nv_bfloat16 g_o  [MROWS * C_];
__device__ __nv_bfloat16 g_wT [1536 * C_];
__device__ __nv_bfloat16 g_woT[C_ * C_];

// ---------------- asm helpers ----------------
__device__ __forceinline__ void mma16816(float* c, uint32_t a0, uint32_t a1, uint32_t a2, uint32_t a3,
                                         uint32_t b0, uint32_t b1) {
    asm volatile(
        "mma.sync.aligned.m16n8k16.row.col.f32.bf16.bf16.f32 "
        "{%0,%1,%2,%3}, {%4,%5,%6,%7}, {%8,%9}, {%0,%1,%2,%3};"
        : "+f"(c[0]), "+f"(c[1]), "+f"(c[2]), "+f"(c[3])
        : "r"(a0), "r"(a1), "r"(a2), "r"(a3), "r"(b0), "r"(b1));
}
__device__ __forceinline__ void ldsm4(uint32_t* r, uint32_t addr) {
    asm volatile("ldmatrix.sync.aligned.m8n8.x4.shared.b16 {%0,%1,%2,%3}, [%4];"
                 : "=r"(r[0]), "=r"(r[1]), "=r"(r[2]), "=r"(r[3]) : "r"(addr));
}
__device__ __forceinline__ void ldsm4t(uint32_t* r, uint32_t addr) {
    asm volatile("ldmatrix.sync.aligned.m8n8.x4.trans.shared.b16 {%0,%1,%2,%3}, [%4];"
                 : "=r"(r[0]), "=r"(r[1]), "=r"(r[2]), "=r"(r[3]) : "r"(addr));
}
__device__ __forceinline__ uint32_t smem_u32(const void* p) {
    return (uint32_t)__cvta_generic_to_shared(p);
}
__device__ __forceinline__ uint32_t pack_bf16(float a, float b) {
    __nv_bfloat162 t = __floats2bfloat162_rn(a, b);
    return *reinterpret_cast<uint32_t*>(&t);
}
__device__ __forceinline__ void cpbulk(uint32_t dst, const void* src, uint32_t bytes, uint32_t mbar) {
    asm volatile("cp.async.bulk.shared::cta.global.mbarrier::complete_tx::bytes [%0], [%1], %2, [%3];"
                 :: "r"(dst), "l"(src), "r"(bytes), "r"(mbar) : "memory");
}
#define MBARRIER_INIT(mbar, count) \
    asm volatile("mbarrier.init.shared.b64 [%0], %1;" :: "r"((uint32_t)(mbar)), "r"((uint32_t)(count)) : "memory")
#define MBARRIER_EXPECT_TX(mbar, tx) \
    asm volatile("mbarrier.arrive.expect_tx.shared.b64 _, [%0], %1;" :: "r"((uint32_t)(mbar)), "r"((uint32_t)(tx)) : "memory")
#define MBARRIER_WAIT_PARITY(mbar, parity) do { \
    uint32_t _mbar = (uint32_t)(mbar); \
    uint32_t _parity = (uint32_t)(parity); \
    uint32_t _done; \
    asm volatile( \
        "{\n\t.reg .pred p;\n\t" \
        "mbarrier.try_wait.parity.acquire.cta.shared::cta.b64 p, [%1], %2;\n\t" \
        "selp.b32 %0, 1, 0, p;\n\t}" \
        : "=r"(_done) : "r"(_mbar), "r"(_parity) : "memory"); \
    if (!_done) { \
        asm volatile( \
            "{\n\t.reg .pred P1;\n\t" \
            "WAIT_LOOP_%=:\n\t" \
            "mbarrier.try_wait.parity.acquire.cta.shared::cta.b64 P1, [%0], %1, 0x989680;\n\t" \
            "@P1 bra.uni WAIT_DONE_%=;\n\t" \
            "bra.uni WAIT_LOOP_%=;\n\t" \
            "WAIT_DONE_%=:\n\t}" \
            :: "r"(_mbar), "r"(_parity) : "memory"); \
    } \
} while(0)

// R10 swizzle: byte address of 16B chunk c (0..3) of logical 64B row `row`.
__device__ __forceinline__ uint32_t sw_addr(int row, int c) {
    return (uint32_t)(((row >> 1) << 7) + (((((row & 1) << 2) | c) ^ ((row >> 1) & 7)) << 4));
}

// ---------------- K0: prep — gather x, tile weights (2 units/thread for MLP) ----------------
__global__ __launch_bounds__(256) void prep_kernel(const float* __restrict__ x,
                                                   const float* __restrict__ wq,
                                                   const float* __restrict__ wk,
                                                   const float* __restrict__ wv,
                                                   const float* __restrict__ wo) {
    int bid = blockIdx.x;
    if (bid < 4096) {
        #pragma unroll
        for (int e = 0; e < 2; e++) {
            int idx = bid * 512 + e * 256 + threadIdx.x;   // 0..2097151
            int gr = idx >> 6, u = idx & 63;
            int win = gr >> 6, t = gr & 63;
            int b = win >> 6, wh = (win >> 3) & 7, ww = win & 7;
            int i = t >> 3, j = t & 7;
            int r  = (wh * 8 + i + 4) & 63;
            int cc = (ww * 8 + j + 4) & 63;
            const float* src = x + (((b * 64 + r) * 64 + cc) << 9) + u * 8;
            float4 f0 = *reinterpret_cast<const float4*>(src);
            float4 f1 = *reinterpret_cast<const float4*>(src + 4);
            uint4 o;
            o.x = pack_bf16(f0.x, f0.y); o.y = pack_bf16(f0.z, f0.w);
            o.z = pack_bf16(f1.x, f1.y); o.w = pack_bf16(f1.z, f1.w);
            int kc = u >> 2, c = u & 3, trow = gr & 63;
            size_t off = (size_t)(win * 16 + kc) * 4096 + sw_addr(trow, c);
            *reinterpret_cast<uint4*>((char*)g_xw + off) = o;
        }
    } else if (bid < 4288) {
        #pragma unroll
        for (int e = 0; e < 2; e++) {
            int idx = (bid - 4096) * 512 + e * 256 + threadIdx.x;  // 0..98303
            int jcol = idx >> 6, u = idx & 63;
            int sel = jcol >> 9, jj = jcol & 511;
            int h = jj >> 6, d = jj & 63;
            const float* w = (sel == 0) ? wq : (sel == 1) ? wk : wv;
            float v[8];
            #pragma unroll
            for (int kk = 0; kk < 8; kk++) v[kk] = w[(u * 8 + kk) * 512 + jj];
            uint4 o;
            o.x = pack_bf16(v[0], v[1]); o.y = pack_bf16(v[2], v[3]);
            o.z = pack_bf16(v[4], v[5]); o.w = pack_bf16(v[6], v[7]);
            int kc = u >> 2, c = u & 3, brow = sel * 64 + d;
            size_t off = (size_t)(h * 16 + kc) * 12288 + sw_addr(brow, c);
            *reinterpret_cast<uint4*>((char*)g_wT + off) = o;
        }
    } else {
        #pragma unroll
        for (int e = 0; e < 2; e++) {
            int idx = (bid - 4288) * 512 + e * 256 + threadIdx.x;  // 0..32767
            int jcol = idx >> 6, u = idx & 63;
            float v[8];
            #pragma unroll
            for (int kk = 0; kk < 8; kk++) v[kk] = wo[(u * 8 + kk) * 512 + jcol];
            uint4 o;
            o.x = pack_bf16(v[0], v[1]); o.y = pack_bf16(v[2], v[3]);
            o.z = pack_bf16(v[4], v[5]); o.w = pack_bf16(v[6], v[7]);
            int kc = u >> 3, c = u & 7, trow = jcol & 127;
            size_t e2 = (size_t)((jcol >> 7) * 8 + kc) * 8192 + trow * 64 + ((c ^ (trow & 7)) << 3);
            *reinterpret_cast<uint4*>(g_woT + e2) = o;
        }
    }
}

// ---------------- K1: FUSED qkv GEMM + attention per (head, window) — unchanged R15 ----------------
#define F_STAGE   16384
#define F_SMEM    (128 + 3 * F_STAGE + 3 * 8192)

__global__ __launch_bounds__(128, 3) void qkv_attn_kernel(const float* __restrict__ bq,
                                                          const float* __restrict__ bk,
                                                          const float* __restrict__ bv) {
    extern __shared__ char dyn[];
    const int head = blockIdx.x, win = blockIdx.y;
    const int tid = threadIdx.x, lane = tid & 31, warp = tid >> 5;
    const int wm = warp >> 1, wn = warp & 1;
    const int g = lane >> 2, tg = lane & 3;

    const uint32_t dsm = (smem_u32(dyn) + 127) & ~127u;
    const uint32_t stg0 = dsm + 128;
    const uint32_t qkv0 = stg0 + 3 * F_STAGE;

    if (tid == 0) {
        MBARRIER_INIT(dsm + 0, 1);
        MBARRIER_INIT(dsm + 8, 1);
        MBARRIER_INIT(dsm + 16, 1);
    }
    __syncthreads();

    const char* Abase = (const char*)g_xw + (size_t)win * 65536;
    const char* Bbase = (const char*)g_wT + (size_t)head * 196608;

    if (tid == 0) {
        MBARRIER_EXPECT_TX(dsm + 0, F_STAGE);
        cpbulk(stg0, Abase, 4096, dsm + 0);
        cpbulk(stg0 + 4096, Bbase, 12288, dsm + 0);
        MBARRIER_EXPECT_TX(dsm + 8, F_STAGE);
        cpbulk(stg0 + F_STAGE, Abase + 4096, 4096, dsm + 8);
        cpbulk(stg0 + F_STAGE + 4096, Bbase + 12288, 12288, dsm + 8);
    }

    float acc[2][12][4];
    #pragma unroll
    for (int mi = 0; mi < 2; mi++)
        #pragma unroll
        for (int nt = 0; nt < 12; nt++)
            #pragma unroll
            for (int e = 0; e < 4; e++) acc[mi][nt][e] = 0.f;

    const int r_a = wm * 32 + (lane & 15);
    const int hiA = lane >> 4;
    const uint32_t aOff0 = sw_addr(r_a, hiA), aOff1 = sw_addr(r_a, hiA + 2);
    const int r_b = wn * 96 + ((lane >> 4) & 1) * 8 + (lane & 7);
    const int hiB = (lane >> 3) & 1;
    const uint32_t bOff0 = sw_addr(r_b, hiB), bOff1 = sw_addr(r_b, hiB + 2);

    for (int kc = 0; kc < 16; kc++) {
        const int s = kc % 3;
        MBARRIER_WAIT_PARITY(dsm + s * 8, (uint32_t)((kc / 3) & 1));
        if (kc < 14 && tid == 0) {
            const int kn = kc + 2, sn = kn % 3;
            MBARRIER_EXPECT_TX(dsm + sn * 8, F_STAGE);
            cpbulk(stg0 + sn * F_STAGE, Abase + kn * 4096, 4096, dsm + sn * 8);
            cpbulk(stg0 + sn * F_STAGE + 4096, Bbase + (size_t)kn * 12288, 12288, dsm + sn * 8);
        }
        const uint32_t sA = stg0 + s * F_STAGE;
        const uint32_t sB = sA + 4096;
        #pragma unroll
        for (int ks = 0; ks < 2; ks++) {
            const uint32_t aOff = sA + (ks ? aOff1 : aOff0);
            const uint32_t bOff = sB + (ks ? bOff1 : bOff0);
            uint32_t a[2][4], bb[6][4];
            #pragma unroll
            for (int mi = 0; mi < 2; mi++)
                ldsm4(a[mi], aOff + mi * 1024);
            #pragma unroll
            for (int p = 0; p < 6; p++)
                ldsm4(bb[p], bOff + p * 1024);
            #pragma unroll
            for (int mi = 0; mi < 2; mi++)
                #pragma unroll
                for (int nt = 0; nt < 12; nt++)
                    mma16816(acc[mi][nt], a[mi][0], a[mi][1], a[mi][2], a[mi][3],
                             bb[nt >> 1][(nt & 1) * 2], bb[nt >> 1][(nt & 1) * 2 + 1]);
        }
        __syncthreads();
    }

    #pragma unroll
    for (int mi = 0; mi < 2; mi++) {
        #pragma unroll
        for (int nt = 0; nt < 12; nt++) {
            const int col = wn * 96 + nt * 8 + 2 * tg;
            const int sel = col >> 6, d = col & 63;
            const float* bias = (sel == 0) ? bq : (sel == 1) ? bk : bv;
            const float b0f = bias[head * 64 + d], b1f = bias[head * 64 + d + 1];
            const uint32_t base = qkv0 + sel * 8192;
            const int row0 = wm * 32 + mi * 16 + g, row1 = row0 + 8;
            const uint32_t a0 = base + row0 * 128 + ((((d >> 3) ^ (row0 & 7))) << 4) + (d & 7) * 2;
            const uint32_t a1 = base + row1 * 128 + ((((d >> 3) ^ (row1 & 7))) << 4) + (d & 7) * 2;
            uint32_t v0 = pack_bf16(acc[mi][nt][0] + b0f, acc[mi][nt][1] + b1f);
            uint32_t v1 = pack_bf16(acc[mi][nt][2] + b0f, acc[mi][nt][3] + b1f);
            asm volatile("st.shared.b32 [%0], %1;" :: "r"(a0), "r"(v0) : "memory");
            asm volatile("st.shared.b32 [%0], %1;" :: "r"(a1), "r"(v1) : "memory");
        }
    }
    __syncthreads();

    const uint32_t Qs = qkv0, Ks = qkv0 + 8192, Vs = qkv0 + 16384;
    const int qRow = warp * 16 + (lane & 15);
    const int hiQ = lane >> 4, swzQ = qRow & 7;
    const uint32_t qBase = Qs + qRow * 128;
    const int kRow = ((lane >> 4) & 1) * 8 + (lane & 7);
    const int hiK = (lane >> 3) & 1, swzK = kRow & 7;
    const uint32_t kBase = Ks + kRow * 128;
    const int vRow = (lane & 7) + ((lane >> 3) & 1) * 8;
    const int hiV = (lane >> 4) & 1, swzV = vRow & 7;
    const uint32_t vBase = Vs + vRow * 128;

    float sc[8][4];
    #pragma unroll
    for (int nt = 0; nt < 8; nt++) { sc[nt][0]=0.f; sc[nt][1]=0.f; sc[nt][2]=0.f; sc[nt][3]=0.f; }
    #pragma unroll
    for (int ks = 0; ks < 4; ks++) {
        uint32_t a[4], bb[4][4];
        ldsm4(a, qBase + (((ks * 2 + hiQ) ^ swzQ) << 4));
        #pragma unroll
        for (int p = 0; p < 4; p++)
            ldsm4(bb[p], kBase + p * 2048 + (((ks * 2 + hiK) ^ swzK) << 4));
        #pragma unroll
        for (int nt = 0; nt < 8; nt++)
            mma16816(sc[nt], a[0], a[1], a[2], a[3],
                     bb[nt >> 1][(nt & 1) * 2], bb[nt >> 1][(nt & 1) * 2 + 1]);
    }

    float mx0 = -1e30f, mx1 = -1e30f;
    #pragma unroll
    for (int nt = 0; nt < 8; nt++) {
        mx0 = fmaxf(mx0, fmaxf(sc[nt][0], sc[nt][1]));
        mx1 = fmaxf(mx1, fmaxf(sc[nt][2], sc[nt][3]));
    }
    mx0 = fmaxf(mx0, __shfl_xor_sync(0xffffffff, mx0, 1));
    mx0 = fmaxf(mx0, __shfl_xor_sync(0xffffffff, mx0, 2));
    mx1 = fmaxf(mx1, __shfl_xor_sync(0xffffffff, mx1, 1));
    mx1 = fmaxf(mx1, __shfl_xor_sync(0xffffffff, mx1, 2));
    float s0 = 0.f, s1 = 0.f;
    #pragma unroll
    for (int nt = 0; nt < 8; nt++) {
        sc[nt][0] = __expf((sc[nt][0] - mx0) * SCALE_);
        sc[nt][1] = __expf((sc[nt][1] - mx0) * SCALE_);
        sc[nt][2] = __expf((sc[nt][2] - mx1) * SCALE_);
        sc[nt][3] = __expf((sc[nt][3] - mx1) * SCALE_);
        s0 += sc[nt][0] + sc[nt][1];
        s1 += sc[nt][2] + sc[nt][3];
    }
    s0 += __shfl_xor_sync(0xffffffff, s0, 1);
    s0 += __shfl_xor_sync(0xffffffff, s0, 2);
    s1 += __shfl_xor_sync(0xffffffff, s1, 1);
    s1 += __shfl_xor_sync(0xffffffff, s1, 2);
    const float i0 = 1.f / s0, i1 = 1.f / s1;

    uint32_t pa[8][2];
    #pragma unroll
    for (int nt = 0; nt < 8; nt++) {
        pa[nt][0] = pack_bf16(sc[nt][0] * i0, sc[nt][1] * i0);
        pa[nt][1] = pack_bf16(sc[nt][2] * i1, sc[nt][3] * i1);
    }

    float oc[8][4];
    #pragma unroll
    for (int nt = 0; nt < 8; nt++) { oc[nt][0]=0.f; oc[nt][1]=0.f; oc[nt][2]=0.f; oc[nt][3]=0.f; }
    #pragma unroll
    for (int ks = 0; ks < 4; ks++) {
        uint32_t bb[4][4];
        #pragma unroll
        for (int p = 0; p < 4; p++)
            ldsm4t(bb[p], vBase + ks * 2048 + (((p * 2 + hiV) ^ swzV) << 4));
        uint32_t a0 = pa[2 * ks][0], a1 = pa[2 * ks][1];
        uint32_t a2 = pa[2 * ks + 1][0], a3 = pa[2 * ks + 1][1];
        #pragma unroll
        for (int nt = 0; nt < 8; nt++)
            mma16816(oc[nt], a0, a1, a2, a3,
                     bb[nt >> 1][(nt & 1) * 2], bb[nt >> 1][(nt & 1) * 2 + 1]);
    }

    const int r0 = warp * 16 + g;
    const size_t tbase = (size_t)((win >> 1) * 8 + head) * 8192;
    const int trow0 = (win & 1) * 64 + r0;
    #pragma unroll
    for (int nt = 0; nt < 8; nt++) {
        const int trow1 = trow0 + 8;
        size_t e0 = tbase + trow0 * 64 + ((nt ^ (trow0 & 7)) << 3) + 2 * tg;
        size_t e1 = tbase + trow1 * 64 + ((nt ^ (trow1 & 7)) << 3) + 2 * tg;
        *reinterpret_cast<uint32_t*>(g_o + e0) = pack_bf16(oc[nt][0], oc[nt][1]);
        *reinterpret_cast<uint32_t*>(g_o + e1) = pack_bf16(oc[nt][2], oc[nt][3]);
    }
}

// ---------------- K3: proj — BM=64, BN=128, BK=64, 128 threads, 2 bulk stages, 4 CTAs/SM ----------------
#define P_STAGE   24576
#define P_SMEM    (128 + 2 * P_STAGE)

__global__ __launch_bounds__(128, 4) void proj_kernel(const float* __restrict__ x,
                                                      const float* __restrict__ bo,
                                                      float* __restrict__ out) {
    extern __shared__ char dyn[];
    const int tid = threadIdx.x, lane = tid & 31, warp = tid >> 5;
    const int g = lane >> 2, tg = lane & 3;
    const int wm = warp >> 1, wn = warp & 1;
    const int mbase = blockIdx.y * 64, nbase = blockIdx.x * 128;

    const uint32_t dsm = (smem_u32(dyn) + 127) & ~127u;
    const uint32_t stg0 = dsm + 128;

    if (tid == 0) {
        MBARRIER_INIT(dsm + 0, 1);
        MBARRIER_INIT(dsm + 8, 1);
    }
    __syncthreads();

    const char* Abase = (const char*)g_o + (size_t)(blockIdx.y >> 1) * 131072
                      + (size_t)(blockIdx.y & 1) * 8192;
    const char* Bbase = (const char*)g_woT + (size_t)blockIdx.x * 131072;

    if (tid == 0) {
        MBARRIER_EXPECT_TX(dsm + 0, P_STAGE);
        cpbulk(stg0, Abase, 8192, dsm + 0);
        cpbulk(stg0 + 8192, Bbase, 16384, dsm + 0);
        MBARRIER_EXPECT_TX(dsm + 8, P_STAGE);
        cpbulk(stg0 + P_STAGE, Abase + 16384, 8192, dsm + 8);
        cpbulk(stg0 + P_STAGE + 8192, Bbase + 16384, 16384, dsm + 8);
    }

    float acc[2][8][4];
    #pragma unroll
    for (int mi = 0; mi < 2; mi++)
        #pragma unroll
        for (int nt = 0; nt < 8; nt++)
            #pragma unroll
            for (int e = 0; e < 4; e++) acc[mi][nt][e] = 0.f;

    const int rowA = wm * 32 + (lane & 15);
    const uint32_t aRow = (uint32_t)rowA * 128;
    const int hiA = lane >> 4, swzA = rowA & 7;
    const int rowB = wn * 64 + ((lane >> 4) & 1) * 8 + (lane & 7);
    const uint32_t bRow = (uint32_t)rowB * 128;
    const int hiB = (lane >> 3) & 1, swzB = rowB & 7;

    for (int kc = 0; kc < 8; kc++) {
        const int s = kc & 1;
        MBARRIER_WAIT_PARITY(dsm + s * 8, (uint32_t)((kc >> 1) & 1));

        const uint32_t sA = stg0 + s * P_STAGE;
        const uint32_t sB = sA + 8192;
        #pragma unroll
        for (int ks = 0; ks < 4; ks++) {
            const uint32_t colA = (uint32_t)(((2 * ks + hiA) ^ swzA) << 4);
            const uint32_t colB = (uint32_t)(((2 * ks + hiB) ^ swzB) << 4);
            uint32_t a[2][4], bb[4][4];
            #pragma unroll
            for (int mi = 0; mi < 2; mi++)
                ldsm4(a[mi], sA + aRow + mi * 2048 + colA);
            #pragma unroll
            for (int p = 0; p < 4; p++)
                ldsm4(bb[p], sB + bRow + p * 2048 + colB);
            #pragma unroll
            for (int mi = 0; mi < 2; mi++)
                #pragma unroll
                for (int nt = 0; nt < 8; nt++)
                    mma16816(acc[mi][nt], a[mi][0], a[mi][1], a[mi][2], a[mi][3],
                             bb[nt >> 1][(nt & 1) * 2], bb[nt >> 1][(nt & 1) * 2 + 1]);
        }
        __syncthreads();    // stage s fully consumed; safe to refill below
        if (kc < 6 && tid == 0) {
            const int kn = kc + 2;
            MBARRIER_EXPECT_TX(dsm + s * 8, P_STAGE);
            cpbulk(stg0 + s * P_STAGE, Abase + kn * 16384, 8192, dsm + s * 8);
            cpbulk(stg0 + s * P_STAGE + 8192, Bbase + kn * 16384, 16384, dsm + s * 8);
        }
    }

    #pragma unroll
    for (int mi = 0; mi < 2; mi++) {
        #pragma unroll
        for (int half = 0; half < 2; half++) {
            int row = mbase + wm * 32 + mi * 16 + g + half * 8;
            int win = row >> 6, t = row & 63;
            int b = win >> 6, wh = (win >> 3) & 7, ww = win & 7;
            int i = t >> 3, j = t & 7;
            int r  = (wh * 8 + i + 4) & 63;
            int cc = (ww * 8 + j + 4) & 63;
            size_t off = (size_t)((b * 64 + r) * 64 + cc) * C_;
            #pragma unroll
            for (int nt = 0; nt < 8; nt++) {
                int col = nbase + wn * 64 + nt * 8 + 2 * tg;
                float2 xr = *reinterpret_cast<const float2*>(x + off + col);
                float2 o;
                o.x = acc[mi][nt][2 * half + 0] + bo[col]     + xr.x;
                o.y = acc[mi][nt][2 * half + 1] + bo[col + 1] + xr.y;
                *reinterpret_cast<float2*>(out + off + col) = o;
            }
        }
    }
}

// ---------------- launch ----------------
extern "C" void kernel_launch(void* const* d_in, const int* in_sizes, int n_in,
                              void* d_out, int out_size) {
    const float* x  = (const float*)d_in[0];
    const float* wq = (const float*)d_in[1];
    const float* bq = (const float*)d_in[2];
    const float* wk = (const float*)d_in[3];
    const float* bk = (const float*)d_in[4];
    const float* wv = (const float*)d_in[5];
    const float* bv = (const float*)d_in[6];
    const float* wo = (const float*)d_in[7];
    const float* bo = (const float*)d_in[8];
    float* out = (float*)d_out;

    cudaFuncSetAttribute(qkv_attn_kernel, cudaFuncAttributeMaxDynamicSharedMemorySize, F_SMEM);
    cudaFuncSetAttribute(proj_kernel, cudaFuncAttributeMaxDynamicSharedMemorySize, P_SMEM);

    prep_kernel<<<4352, 256>>>(x, wq, wk, wv, wo);
    dim3 g1(8, 512);
    qkv_attn_kernel<<<g1, 128, F_SMEM>>>(bq, bk, bv);
    dim3 g3(4, 512);
    proj_kernel<<<g3, 128, P_SMEM>>>(x, bo, out);
}

// round 17
// speedup vs baseline: 1.6254x; 1.0094x over previous
#include <cuda_runtime.h>
#include <cuda_bf16.h>
#include <stdint.h>

#define NWIN   512
#define T_     64
#define C_     512
#define NH_    8
#define D_     64
#define MROWS  32768
#define SCALE_ 0.125f

// ---------------- scratch ----------------
// g_xw: per-window tiles [win 512][kc 16] of 64 rows x 32 bf16 (4KB, R10-swizzled)
// g_wT: per-head tiles   [head 8][kc 16] of 192 rows (q|k|v cols) x 32 bf16 (12KB, R10-swizzled)
// g_o / g_woT: R12 format — [rowblk][kc64] 16KB tiles of 128 rows x 64 bf16, SW128
__device__ __nv_bfloat16 g_xw [MROWS * C_];
__device__ __nv_bfloat16 g_o  [MROWS * C_];
__device__ __nv_bfloat16 g_wT [1536 * C_];
__device__ __nv_bfloat16 g_woT[C_ * C_];

// ---------------- asm helpers ----------------
__device__ __forceinline__ void mma16816(float* c, uint32_t a0, uint32_t a1, uint32_t a2, uint32_t a3,
                                         uint32_t b0, uint32_t b1) {
    asm volatile(
        "mma.sync.aligned.m16n8k16.row.col.f32.bf16.bf16.f32 "
        "{%0,%1,%2,%3}, {%4,%5,%6,%7}, {%8,%9}, {%0,%1,%2,%3};"
        : "+f"(c[0]), "+f"(c[1]), "+f"(c[2]), "+f"(c[3])
        : "r"(a0), "r"(a1), "r"(a2), "r"(a3), "r"(b0), "r"(b1));
}
__device__ __forceinline__ void ldsm4(uint32_t* r, uint32_t addr) {
    asm volatile("ldmatrix.sync.aligned.m8n8.x4.shared.b16 {%0,%1,%2,%3}, [%4];"
                 : "=r"(r[0]), "=r"(r[1]), "=r"(r[2]), "=r"(r[3]) : "r"(addr));
}
__device__ __forceinline__ void ldsm4t(uint32_t* r, uint32_t addr) {
    asm volatile("ldmatrix.sync.aligned.m8n8.x4.trans.shared.b16 {%0,%1,%2,%3}, [%4];"
                 : "=r"(r[0]), "=r"(r[1]), "=r"(r[2]), "=r"(r[3]) : "r"(addr));
}
__device__ __forceinline__ uint32_t smem_u32(const void* p) {
    return (uint32_t)__cvta_generic_to_shared(p);
}
__device__ __forceinline__ uint32_t pack_bf16(float a, float b) {
    __nv_bfloat162 t = __floats2bfloat162_rn(a, b);
    return *reinterpret_cast<uint32_t*>(&t);
}
__device__ __forceinline__ void cpbulk(uint32_t dst, const void* src, uint32_t bytes, uint32_t mbar) {
    asm volatile("cp.async.bulk.shared::cta.global.mbarrier::complete_tx::bytes [%0], [%1], %2, [%3];"
                 :: "r"(dst), "l"(src), "r"(bytes), "r"(mbar) : "memory");
}
#define MBARRIER_INIT(mbar, count) \
    asm volatile("mbarrier.init.shared.b64 [%0], %1;" :: "r"((uint32_t)(mbar)), "r"((uint32_t)(count)) : "memory")
#define MBARRIER_EXPECT_TX(mbar, tx) \
    asm volatile("mbarrier.arrive.expect_tx.shared.b64 _, [%0], %1;" :: "r"((uint32_t)(mbar)), "r"((uint32_t)(tx)) : "memory")
#define MBARRIER_WAIT_PARITY(mbar, parity) do { \
    uint32_t _mbar = (uint32_t)(mbar); \
    uint32_t _parity = (uint32_t)(parity); \
    uint32_t _done; \
    asm volatile( \
        "{\n\t.reg .pred p;\n\t" \
        "mbarrier.try_wait.parity.acquire.cta.shared::cta.b64 p, [%1], %2;\n\t" \
        "selp.b32 %0, 1, 0, p;\n\t}" \
        : "=r"(_done) : "r"(_mbar), "r"(_parity) : "memory"); \
    if (!_done) { \
        asm volatile( \
            "{\n\t.reg .pred P1;\n\t" \
            "WAIT_LOOP_%=:\n\t" \
            "mbarrier.try_wait.parity.acquire.cta.shared::cta.b64 P1, [%0], %1, 0x989680;\n\t" \
            "@P1 bra.uni WAIT_DONE_%=;\n\t" \
            "bra.uni WAIT_LOOP_%=;\n\t" \
            "WAIT_DONE_%=:\n\t}" \
            :: "r"(_mbar), "r"(_parity) : "memory"); \
    } \
} while(0)

// R10 swizzle: byte address of 16B chunk c (0..3) of logical 64B row `row`.
__device__ __forceinline__ uint32_t sw_addr(int row, int c) {
    return (uint32_t)(((row >> 1) << 7) + (((((row & 1) << 2) | c) ^ ((row >> 1) & 7)) << 4));
}

// ---------------- K0: prep — gather x, tile weights (R15 form) ----------------
__global__ __launch_bounds__(256) void prep_kernel(const float* __restrict__ x,
                                                   const float* __restrict__ wq,
                                                   const float* __restrict__ wk,
                                                   const float* __restrict__ wv,
                                                   const float* __restrict__ wo) {
    int bid = blockIdx.x;
    if (bid < 8192) {
        int idx = bid * 256 + threadIdx.x;        // 0..2097151
        int gr = idx >> 6, u = idx & 63;
        int win = gr >> 6, t = gr & 63;
        int b = win >> 6, wh = (win >> 3) & 7, ww = win & 7;
        int i = t >> 3, j = t & 7;
        int r  = (wh * 8 + i + 4) & 63;
        int cc = (ww * 8 + j + 4) & 63;
        const float* src = x + (((b * 64 + r) * 64 + cc) << 9) + u * 8;
        float4 f0 = *reinterpret_cast<const float4*>(src);
        float4 f1 = *reinterpret_cast<const float4*>(src + 4);
        uint4 o;
        o.x = pack_bf16(f0.x, f0.y); o.y = pack_bf16(f0.z, f0.w);
        o.z = pack_bf16(f1.x, f1.y); o.w = pack_bf16(f1.z, f1.w);
        int kc = u >> 2, c = u & 3, trow = gr & 63;
        size_t off = (size_t)(win * 16 + kc) * 4096 + sw_addr(trow, c);
        *reinterpret_cast<uint4*>((char*)g_xw + off) = o;
    } else if (bid < 8576) {
        int idx = (bid - 8192) * 256 + threadIdx.x;  // 0..98303
        int jcol = idx >> 6, u = idx & 63;
        int sel = jcol >> 9, jj = jcol & 511;
        int h = jj >> 6, d = jj & 63;
        const float* w = (sel == 0) ? wq : (sel == 1) ? wk : wv;
        float v[8];
        #pragma unroll
        for (int kk = 0; kk < 8; kk++) v[kk] = w[(u * 8 + kk) * 512 + jj];
        uint4 o;
        o.x = pack_bf16(v[0], v[1]); o.y = pack_bf16(v[2], v[3]);
        o.z = pack_bf16(v[4], v[5]); o.w = pack_bf16(v[6], v[7]);
        int kc = u >> 2, c = u & 3, brow = sel * 64 + d;
        size_t off = (size_t)(h * 16 + kc) * 12288 + sw_addr(brow, c);
        *reinterpret_cast<uint4*>((char*)g_wT + off) = o;
    } else {
        int idx = (bid - 8576) * 256 + threadIdx.x;  // 0..32767
        int jcol = idx >> 6, u = idx & 63;
        float v[8];
        #pragma unroll
        for (int kk = 0; kk < 8; kk++) v[kk] = wo[(u * 8 + kk) * 512 + jcol];
        uint4 o;
        o.x = pack_bf16(v[0], v[1]); o.y = pack_bf16(v[2], v[3]);
        o.z = pack_bf16(v[4], v[5]); o.w = pack_bf16(v[6], v[7]);
        int kc = u >> 3, c = u & 7, trow = jcol & 127;
        size_t e = (size_t)((jcol >> 7) * 8 + kc) * 8192 + trow * 64 + ((c ^ (trow & 7)) << 3);
        *reinterpret_cast<uint4*>(g_woT + e) = o;
    }
}

// ---------------- K1: FUSED qkv GEMM + attention per (head, window) — unchanged ----------------
#define F_STAGE   16384
#define F_SMEM    (128 + 3 * F_STAGE + 3 * 8192)

__global__ __launch_bounds__(128, 3) void qkv_attn_kernel(const float* __restrict__ bq,
                                                          const float* __restrict__ bk,
                                                          const float* __restrict__ bv) {
    extern __shared__ char dyn[];
    const int head = blockIdx.x, win = blockIdx.y;
    const int tid = threadIdx.x, lane = tid & 31, warp = tid >> 5;
    const int wm = warp >> 1, wn = warp & 1;
    const int g = lane >> 2, tg = lane & 3;

    const uint32_t dsm = (smem_u32(dyn) + 127) & ~127u;
    const uint32_t stg0 = dsm + 128;
    const uint32_t qkv0 = stg0 + 3 * F_STAGE;

    if (tid == 0) {
        MBARRIER_INIT(dsm + 0, 1);
        MBARRIER_INIT(dsm + 8, 1);
        MBARRIER_INIT(dsm + 16, 1);
    }
    __syncthreads();

    const char* Abase = (const char*)g_xw + (size_t)win * 65536;
    const char* Bbase = (const char*)g_wT + (size_t)head * 196608;

    if (tid == 0) {
        MBARRIER_EXPECT_TX(dsm + 0, F_STAGE);
        cpbulk(stg0, Abase, 4096, dsm + 0);
        cpbulk(stg0 + 4096, Bbase, 12288, dsm + 0);
        MBARRIER_EXPECT_TX(dsm + 8, F_STAGE);
        cpbulk(stg0 + F_STAGE, Abase + 4096, 4096, dsm + 8);
        cpbulk(stg0 + F_STAGE + 4096, Bbase + 12288, 12288, dsm + 8);
    }

    float acc[2][12][4];
    #pragma unroll
    for (int mi = 0; mi < 2; mi++)
        #pragma unroll
        for (int nt = 0; nt < 12; nt++)
            #pragma unroll
            for (int e = 0; e < 4; e++) acc[mi][nt][e] = 0.f;

    const int r_a = wm * 32 + (lane & 15);
    const int hiA = lane >> 4;
    const uint32_t aOff0 = sw_addr(r_a, hiA), aOff1 = sw_addr(r_a, hiA + 2);
    const int r_b = wn * 96 + ((lane >> 4) & 1) * 8 + (lane & 7);
    const int hiB = (lane >> 3) & 1;
    const uint32_t bOff0 = sw_addr(r_b, hiB), bOff1 = sw_addr(r_b, hiB + 2);

    for (int kc = 0; kc < 16; kc++) {
        const int s = kc % 3;
        MBARRIER_WAIT_PARITY(dsm + s * 8, (uint32_t)((kc / 3) & 1));
        if (kc < 14 && tid == 0) {
            const int kn = kc + 2, sn = kn % 3;
            MBARRIER_EXPECT_TX(dsm + sn * 8, F_STAGE);
            cpbulk(stg0 + sn * F_STAGE, Abase + kn * 4096, 4096, dsm + sn * 8);
            cpbulk(stg0 + sn * F_STAGE + 4096, Bbase + (size_t)kn * 12288, 12288, dsm + sn * 8);
        }
        const uint32_t sA = stg0 + s * F_STAGE;
        const uint32_t sB = sA + 4096;
        #pragma unroll
        for (int ks = 0; ks < 2; ks++) {
            const uint32_t aOff = sA + (ks ? aOff1 : aOff0);
            const uint32_t bOff = sB + (ks ? bOff1 : bOff0);
            uint32_t a[2][4], bb[6][4];
            #pragma unroll
            for (int mi = 0; mi < 2; mi++)
                ldsm4(a[mi], aOff + mi * 1024);
            #pragma unroll
            for (int p = 0; p < 6; p++)
                ldsm4(bb[p], bOff + p * 1024);
            #pragma unroll
            for (int mi = 0; mi < 2; mi++)
                #pragma unroll
                for (int nt = 0; nt < 12; nt++)
                    mma16816(acc[mi][nt], a[mi][0], a[mi][1], a[mi][2], a[mi][3],
                             bb[nt >> 1][(nt & 1) * 2], bb[nt >> 1][(nt & 1) * 2 + 1]);
        }
        __syncthreads();
    }

    #pragma unroll
    for (int mi = 0; mi < 2; mi++) {
        #pragma unroll
        for (int nt = 0; nt < 12; nt++) {
            const int col = wn * 96 + nt * 8 + 2 * tg;
            const int sel = col >> 6, d = col & 63;
            const float* bias = (sel == 0) ? bq : (sel == 1) ? bk : bv;
            const float b0f = bias[head * 64 + d], b1f = bias[head * 64 + d + 1];
            const uint32_t base = qkv0 + sel * 8192;
            const int row0 = wm * 32 + mi * 16 + g, row1 = row0 + 8;
            const uint32_t a0 = base + row0 * 128 + ((((d >> 3) ^ (row0 & 7))) << 4) + (d & 7) * 2;
            const uint32_t a1 = base + row1 * 128 + ((((d >> 3) ^ (row1 & 7))) << 4) + (d & 7) * 2;
            uint32_t v0 = pack_bf16(acc[mi][nt][0] + b0f, acc[mi][nt][1] + b1f);
            uint32_t v1 = pack_bf16(acc[mi][nt][2] + b0f, acc[mi][nt][3] + b1f);
            asm volatile("st.shared.b32 [%0], %1;" :: "r"(a0), "r"(v0) : "memory");
            asm volatile("st.shared.b32 [%0], %1;" :: "r"(a1), "r"(v1) : "memory");
        }
    }
    __syncthreads();

    const uint32_t Qs = qkv0, Ks = qkv0 + 8192, Vs = qkv0 + 16384;
    const int qRow = warp * 16 + (lane & 15);
    const int hiQ = lane >> 4, swzQ = qRow & 7;
    const uint32_t qBase = Qs + qRow * 128;
    const int kRow = ((lane >> 4) & 1) * 8 + (lane & 7);
    const int hiK = (lane >> 3) & 1, swzK = kRow & 7;
    const uint32_t kBase = Ks + kRow * 128;
    const int vRow = (lane & 7) + ((lane >> 3) & 1) * 8;
    const int hiV = (lane >> 4) & 1, swzV = vRow & 7;
    const uint32_t vBase = Vs + vRow * 128;

    float sc[8][4];
    #pragma unroll
    for (int nt = 0; nt < 8; nt++) { sc[nt][0]=0.f; sc[nt][1]=0.f; sc[nt][2]=0.f; sc[nt][3]=0.f; }
    #pragma unroll
    for (int ks = 0; ks < 4; ks++) {
        uint32_t a[4], bb[4][4];
        ldsm4(a, qBase + (((ks * 2 + hiQ) ^ swzQ) << 4));
        #pragma unroll
        for (int p = 0; p < 4; p++)
            ldsm4(bb[p], kBase + p * 2048 + (((ks * 2 + hiK) ^ swzK) << 4));
        #pragma unroll
        for (int nt = 0; nt < 8; nt++)
            mma16816(sc[nt], a[0], a[1], a[2], a[3],
                     bb[nt >> 1][(nt & 1) * 2], bb[nt >> 1][(nt & 1) * 2 + 1]);
    }

    float mx0 = -1e30f, mx1 = -1e30f;
    #pragma unroll
    for (int nt = 0; nt < 8; nt++) {
        mx0 = fmaxf(mx0, fmaxf(sc[nt][0], sc[nt][1]));
        mx1 = fmaxf(mx1, fmaxf(sc[nt][2], sc[nt][3]));
    }
    mx0 = fmaxf(mx0, __shfl_xor_sync(0xffffffff, mx0, 1));
    mx0 = fmaxf(mx0, __shfl_xor_sync(0xffffffff, mx0, 2));
    mx1 = fmaxf(mx1, __shfl_xor_sync(0xffffffff, mx1, 1));
    mx1 = fmaxf(mx1, __shfl_xor_sync(0xffffffff, mx1, 2));
    float s0 = 0.f, s1 = 0.f;
    #pragma unroll
    for (int nt = 0; nt < 8; nt++) {
        sc[nt][0] = __expf((sc[nt][0] - mx0) * SCALE_);
        sc[nt][1] = __expf((sc[nt][1] - mx0) * SCALE_);
        sc[nt][2] = __expf((sc[nt][2] - mx1) * SCALE_);
        sc[nt][3] = __expf((sc[nt][3] - mx1) * SCALE_);
        s0 += sc[nt][0] + sc[nt][1];
        s1 += sc[nt][2] + sc[nt][3];
    }
    s0 += __shfl_xor_sync(0xffffffff, s0, 1);
    s0 += __shfl_xor_sync(0xffffffff, s0, 2);
    s1 += __shfl_xor_sync(0xffffffff, s1, 1);
    s1 += __shfl_xor_sync(0xffffffff, s1, 2);
    const float i0 = 1.f / s0, i1 = 1.f / s1;

    uint32_t pa[8][2];
    #pragma unroll
    for (int nt = 0; nt < 8; nt++) {
        pa[nt][0] = pack_bf16(sc[nt][0] * i0, sc[nt][1] * i0);
        pa[nt][1] = pack_bf16(sc[nt][2] * i1, sc[nt][3] * i1);
    }

    float oc[8][4];
    #pragma unroll
    for (int nt = 0; nt < 8; nt++) { oc[nt][0]=0.f; oc[nt][1]=0.f; oc[nt][2]=0.f; oc[nt][3]=0.f; }
    #pragma unroll
    for (int ks = 0; ks < 4; ks++) {
        uint32_t bb[4][4];
        #pragma unroll
        for (int p = 0; p < 4; p++)
            ldsm4t(bb[p], vBase + ks * 2048 + (((p * 2 + hiV) ^ swzV) << 4));
        uint32_t a0 = pa[2 * ks][0], a1 = pa[2 * ks][1];
        uint32_t a2 = pa[2 * ks + 1][0], a3 = pa[2 * ks + 1][1];
        #pragma unroll
        for (int nt = 0; nt < 8; nt++)
            mma16816(oc[nt], a0, a1, a2, a3,
                     bb[nt >> 1][(nt & 1) * 2], bb[nt >> 1][(nt & 1) * 2 + 1]);
    }

    const int r0 = warp * 16 + g;
    const size_t tbase = (size_t)((win >> 1) * 8 + head) * 8192;
    const int trow0 = (win & 1) * 64 + r0;
    #pragma unroll
    for (int nt = 0; nt < 8; nt++) {
        const int trow1 = trow0 + 8;
        size_t e0 = tbase + trow0 * 64 + ((nt ^ (trow0 & 7)) << 3) + 2 * tg;
        size_t e1 = tbase + trow1 * 64 + ((nt ^ (trow1 & 7)) << 3) + 2 * tg;
        *reinterpret_cast<uint32_t*>(g_o + e0) = pack_bf16(oc[nt][0], oc[nt][1]);
        *reinterpret_cast<uint32_t*>(g_o + e1) = pack_bf16(oc[nt][2], oc[nt][3]);
    }
}

// ---------------- K3: proj — BM=64, BN=128, BK=64, 128 threads, 2 bulk stages, 4 CTAs/SM ----------------
#define P_STAGE   24576
#define P_SMEM    (128 + 2 * P_STAGE)

__global__ __launch_bounds__(128, 4) void proj_kernel(const float* __restrict__ x,
                                                      const float* __restrict__ bo,
                                                      float* __restrict__ out) {
    extern __shared__ char dyn[];
    const int tid = threadIdx.x, lane = tid & 31, warp = tid >> 5;
    const int g = lane >> 2, tg = lane & 3;
    const int wm = warp >> 1, wn = warp & 1;
    const int mbase = blockIdx.y * 64, nbase = blockIdx.x * 128;

    const uint32_t dsm = (smem_u32(dyn) + 127) & ~127u;
    const uint32_t stg0 = dsm + 128;

    if (tid == 0) {
        MBARRIER_INIT(dsm + 0, 1);
        MBARRIER_INIT(dsm + 8, 1);
    }
    __syncthreads();

    const char* Abase = (const char*)g_o + (size_t)(blockIdx.y >> 1) * 131072
                      + (size_t)(blockIdx.y & 1) * 8192;
    const char* Bbase = (const char*)g_woT + (size_t)blockIdx.x * 131072;

    if (tid == 0) {
        MBARRIER_EXPECT_TX(dsm + 0, P_STAGE);
        cpbulk(stg0, Abase, 8192, dsm + 0);
        cpbulk(stg0 + 8192, Bbase, 16384, dsm + 0);
        MBARRIER_EXPECT_TX(dsm + 8, P_STAGE);
        cpbulk(stg0 + P_STAGE, Abase + 16384, 8192, dsm + 8);
        cpbulk(stg0 + P_STAGE + 8192, Bbase + 16384, 16384, dsm + 8);
    }

    float acc[2][8][4];
    #pragma unroll
    for (int mi = 0; mi < 2; mi++)
        #pragma unroll
        for (int nt = 0; nt < 8; nt++)
            #pragma unroll
            for (int e = 0; e < 4; e++) acc[mi][nt][e] = 0.f;

    const int rowA = wm * 32 + (lane & 15);
    const uint32_t aRow = (uint32_t)rowA * 128;
    const int hiA = lane >> 4, swzA = rowA & 7;
    const int rowB = wn * 64 + ((lane >> 4) & 1) * 8 + (lane & 7);
    const uint32_t bRow = (uint32_t)rowB * 128;
    const int hiB = (lane >> 3) & 1, swzB = rowB & 7;

    for (int kc = 0; kc < 8; kc++) {
        const int s = kc & 1;
        MBARRIER_WAIT_PARITY(dsm + s * 8, (uint32_t)((kc >> 1) & 1));

        const uint32_t sA = stg0 + s * P_STAGE;
        const uint32_t sB = sA + 8192;
        #pragma unroll
        for (int ks = 0; ks < 4; ks++) {
            const uint32_t colA = (uint32_t)(((2 * ks + hiA) ^ swzA) << 4);
            const uint32_t colB = (uint32_t)(((2 * ks + hiB) ^ swzB) << 4);
            uint32_t a[2][4], bb[4][4];
            #pragma unroll
            for (int mi = 0; mi < 2; mi++)
                ldsm4(a[mi], sA + aRow + mi * 2048 + colA);
            #pragma unroll
            for (int p = 0; p < 4; p++)
                ldsm4(bb[p], sB + bRow + p * 2048 + colB);
            #pragma unroll
            for (int mi = 0; mi < 2; mi++)
                #pragma unroll
                for (int nt = 0; nt < 8; nt++)
                    mma16816(acc[mi][nt], a[mi][0], a[mi][1], a[mi][2], a[mi][3],
                             bb[nt >> 1][(nt & 1) * 2], bb[nt >> 1][(nt & 1) * 2 + 1]);
        }
        __syncthreads();
        if (kc < 6 && tid == 0) {
            const int kn = kc + 2;
            MBARRIER_EXPECT_TX(dsm + s * 8, P_STAGE);
            cpbulk(stg0 + s * P_STAGE, Abase + kn * 16384, 8192, dsm + s * 8);
            cpbulk(stg0 + s * P_STAGE + 8192, Bbase + kn * 16384, 16384, dsm + s * 8);
        }
    }

    #pragma unroll
    for (int mi = 0; mi < 2; mi++) {
        #pragma unroll
        for (int half = 0; half < 2; half++) {
            int row = mbase + wm * 32 + mi * 16 + g + half * 8;
            int win = row >> 6, t = row & 63;
            int b = win >> 6, wh = (win >> 3) & 7, ww = win & 7;
            int i = t >> 3, j = t & 7;
            int r  = (wh * 8 + i + 4) & 63;
            int cc = (ww * 8 + j + 4) & 63;
            size_t off = (size_t)((b * 64 + r) * 64 + cc) * C_;
            #pragma unroll
            for (int nt = 0; nt < 8; nt++) {
                int col = nbase + wn * 64 + nt * 8 + 2 * tg;
                float2 xr = *reinterpret_cast<const float2*>(x + off + col);
                float2 o;
                o.x = acc[mi][nt][2 * half + 0] + bo[col]     + xr.x;
                o.y = acc[mi][nt][2 * half + 1] + bo[col + 1] + xr.y;
                *reinterpret_cast<float2*>(out + off + col) = o;
            }
        }
    }
}

// ---------------- launch ----------------
extern "C" void kernel_launch(void* const* d_in, const int* in_sizes, int n_in,
                              void* d_out, int out_size) {
    const float* x  = (const float*)d_in[0];
    const float* wq = (const float*)d_in[1];
    const float* bq = (const float*)d_in[2];
    const float* wk = (const float*)d_in[3];
    const float* bk = (const float*)d_in[4];
    const float* wv = (const float*)d_in[5];
    const float* bv = (const float*)d_in[6];
    const float* wo = (const float*)d_in[7];
    const float* bo = (const float*)d_in[8];
    float* out = (float*)d_out;

    cudaFuncSetAttribute(qkv_attn_kernel, cudaFuncAttributeMaxDynamicSharedMemorySize, F_SMEM);
    cudaFuncSetAttribute(proj_kernel, cudaFuncAttributeMaxDynamicSharedMemorySize, P_SMEM);

    prep_kernel<<<8704, 256>>>(x, wq, wk, wv, wo);
    dim3 g1(8, 512);
    qkv_attn_kernel<<<g1, 128, F_SMEM>>>(bq, bk, bv);
    dim3 g3(4, 512);
    proj_kernel<<<g3, 128, P_SMEM>>>(x, bo, out);
}